// round 12
// baseline (speedup 1.0000x reference)
#include <cuda_runtime.h>
#include <cuda_bf16.h>

#define NN   76800
#define EE   1425408
#define BB   1024
#define EPG  1392
#define S1C  36864
#define S2C  25600

// ---------------- device scratch ----------------
__device__ float g_x2[S1C*32];
__device__ __nv_bfloat16 g_x2h[S1C*32];
__device__ float g_cnt1[S1C];
__device__ float g_ppos1[S1C*2];
__device__ unsigned g_el1[EE];
__device__ int   g_ecnt1[BB];
__device__ float g_deg2[S1C];
__device__ __nv_bfloat16 g_acc2h[S1C*25*32];
__device__ float g_x2o[S1C*64];
__device__ float g_x3[S2C*64];
__device__ __nv_bfloat16 g_x3h[S2C*64];
__device__ float g_cnt2[S2C];
__device__ float g_ppos2[S2C*2];
__device__ unsigned g_el2[EE];
__device__ int   g_ecnt2[BB];
__device__ float g_deg3[S2C];
__device__ __nv_bfloat16 g_acc3h[S2C*25*64];
__device__ float g_x3o[S2C*64];
__device__ unsigned g_amax[4];
__device__ unsigned g_Wp2[416*64];
__device__ unsigned g_Wp3[832*64];

// ---------------- helpers ----------------
__device__ __forceinline__ unsigned encf(float f){
    unsigned u=__float_as_uint(f);
    return (u&0x80000000u)? ~u : (u|0x80000000u);
}
__device__ __forceinline__ float decf(unsigned u){
    return (u&0x80000000u)? __uint_as_float(u&0x7FFFFFFFu) : __uint_as_float(~u);
}
__device__ __forceinline__ float eluf(float x){ return x>0.f ? x : expm1f(x); }
__device__ __forceinline__ void redMaxU(unsigned* p, unsigned v){
    asm volatile("red.global.max.u32 [%0], %1;" :: "l"(p), "r"(v) : "memory");
}
__device__ __forceinline__ unsigned packbf(float a, float b){
    __nv_bfloat162 h=__floats2bfloat162_rn(a,b);
    return *reinterpret_cast<unsigned*>(&h);
}
__device__ __forceinline__ unsigned packbf2w(float hi, float lo){
    unsigned h=(unsigned)__bfloat16_as_ushort(__float2bfloat16(hi));
    unsigned l=(unsigned)__bfloat16_as_ushort(__float2bfloat16(lo));
    return (h<<16)|l;
}
__device__ __forceinline__ float upperf(unsigned u){ return __uint_as_float(u&0xFFFF0000u); }
__device__ __forceinline__ float lowerf(unsigned u){ return __uint_as_float(u<<16); }
__device__ __forceinline__ void mma_bf16(float* d, unsigned a0,unsigned a1,unsigned a2,unsigned a3,
                                         unsigned b0, unsigned b1){
    asm("mma.sync.aligned.m16n8k16.row.col.f32.bf16.bf16.f32 "
        "{%0,%1,%2,%3}, {%4,%5,%6,%7}, {%8,%9}, {%0,%1,%2,%3};"
        : "+f"(d[0]),"+f"(d[1]),"+f"(d[2]),"+f"(d[3])
        : "r"(a0),"r"(a1),"r"(a2),"r"(a3),"r"(b0),"r"(b1));
}

// ---------------- pack weights + amax reset ----------------
__global__ void k_prepW(const float* __restrict__ W2, const float* __restrict__ r2,
                        const float* __restrict__ W3, const float* __restrict__ r3){
    int i=blockIdx.x*blockDim.x+threadIdx.x;
    if(i<4) g_amax[i]=0u;
    if(i<416*64){
        int kp=i>>6, n=i&63;
        float lo,hi;
        if(kp<400){ lo=W2[(2*kp)*64+n]; hi=W2[(2*kp+1)*64+n]; }
        else      { int q=kp-400; lo=r2[(2*q)*64+n]; hi=r2[(2*q+1)*64+n]; }
        g_Wp2[i]=packbf(lo,hi);
    }
    int j=i-416*64;
    if(j>=0 && j<832*64){
        int kp=j>>6, n=j&63;
        float lo,hi;
        if(kp<800){ lo=W3[(2*kp)*64+n]; hi=W3[(2*kp+1)*64+n]; }
        else      { int q=kp-800; lo=r3[(2*q)*64+n]; hi=r3[(2*q+1)*64+n]; }
        g_Wp3[j]=packbf(lo,hi);
    }
}

// ---------------- stage-1 global amax ----------------
__global__ void k_amax0g(const float* __restrict__ pos, const int* __restrict__ src,
                         const int* __restrict__ dst){
    int g=blockIdx.x, t=threadIdx.x;
    __shared__ unsigned wm[8];
    unsigned cand=0u;
    for(int i=t;i<EPG;i+=256){
        int e=g*EPG+i;
        int s=src[e], d=dst[e];
        float c0=fabsf(pos[2*s]-pos[2*d]);
        float c1=fabsf(pos[2*s+1]-pos[2*d+1]);
        cand=max(cand,__float_as_uint(fmaxf(c0,c1)));
    }
    unsigned m=__reduce_max_sync(0xffffffffu,cand);
    if((t&31)==0) wm[t>>5]=m;
    __syncthreads();
    if(t==0){
        unsigned mm=0;
        #pragma unroll
        for(int i=0;i<8;i++) mm=max(mm,wm[i]);
        redMaxU(&g_amax[0],mm);
    }
}

// ---------------- fused stage 1: scatter + conv1 + pool1 + dedup1 ----------------
__global__ __launch_bounds__(256) void k_stage1(const float* __restrict__ x,
        const float* __restrict__ pos, const int* __restrict__ src,
        const int* __restrict__ dst, const float* __restrict__ W1,
        const float* __restrict__ r1, const float* __restrict__ b1){
    int g=blockIdx.x, t=threadIdx.x;
    __shared__ float acc[75*25];
    __shared__ float deg[75];
    __shared__ float posx[75], posy[75], xin[75];
    __shared__ float W1s[800], r1s[32], b1s[32];
    __shared__ unsigned px[36*32];
    __shared__ float cnt[36], psx[36], psy[36], ppx[36], ppy[36], deg2s[36];
    __shared__ unsigned char cl[75];
    __shared__ unsigned bm[41];
    __shared__ int ecnt;
    __shared__ unsigned cmax;

    for(int i=t;i<1875;i+=256) acc[i]=0.f;
    for(int i=t;i<800;i+=256) W1s[i]=W1[i];
    if(t<75){
        deg[t]=0.f;
        float2 p=*(const float2*)&pos[(g*75+t)*2];
        posx[t]=p.x; posy[t]=p.y;
        xin[t]=x[g*75+t];
    }
    if(t>=96 && t<128){ r1s[t-96]=r1[t-96]; b1s[t-96]=b1[t-96]; }
    if(t>=128 && t<164){ int c=t-128; cnt[c]=0.f; psx[c]=0.f; psy[c]=0.f; deg2s[c]=0.f; }
    if(t>=164 && t<205) bm[t-164]=0u;
    if(t==0){ ecnt=0; cmax=0u; }
    for(int i=t;i<1152;i+=256) px[i]=encf(-1e30f);
    __syncthreads();
    if(t<75){
        int c0=min(max((int)floorf(posx[t]/5.f),0),5);
        int c1=min(max((int)floorf(posy[t]/5.f),0),5);
        int c=c1*6+c0;
        cl[t]=(unsigned char)c;
        atomicAdd(&cnt[c],1.f);
        atomicAdd(&psx[c],posx[t]);
        atomicAdd(&psy[c],posy[t]);
    }
    __syncthreads();
    if(t<36){
        float ic=1.f/fmaxf(cnt[t],1.f);
        ppx[t]=psx[t]*ic; ppy[t]=psy[t]*ic;
    }
    __syncthreads();
    float amax=fmaxf(__uint_as_float(g_amax[0]),1e-12f);
    float inv=0.5f/amax;
    for(int i=t;i<EPG;i+=256){
        int e=g*EPG+i;
        int s=src[e]-g*75, d=dst[e]-g*75;
        float p0=(posx[s]-posx[d])*inv+0.5f;
        float p1=(posy[s]-posy[d])*inv+0.5f;
        float v0=fminf(fmaxf(p0,0.f),1.f)*4.f;
        float v1=fminf(fmaxf(p1,0.f),1.f)*4.f;
        float b0=fminf(floorf(v0),3.f), b1f=fminf(floorf(v1),3.f);
        int i0=(int)b0, i1=(int)b1f;
        float f0=v0-b0, f1=v1-b1f;
        float xs=xin[s];
        float* base=&acc[d*25+i0+5*i1];
        atomicAdd(base,   (1.f-f0)*(1.f-f1)*xs);
        atomicAdd(base+1, f0*(1.f-f1)*xs);
        atomicAdd(base+5, (1.f-f0)*f1*xs);
        atomicAdd(base+6, f0*f1*xs);
        atomicAdd(&deg[d],1.f);
        int a=cl[s], b=cl[d];
        if(a!=b){
            int key=a*36+b;
            unsigned bit=1u<<(key&31);
            if(!(atomicOr(&bm[key>>5],bit)&bit)){
                int idx=atomicAdd(&ecnt,1);
                g_el1[g*EPG+idx]=(unsigned)a|((unsigned)b<<8);
                atomicAdd(&deg2s[b],1.f);
                float c0=fabsf(ppx[a]-ppx[b]), c1=fabsf(ppy[a]-ppy[b]);
                atomicMax(&cmax,__float_as_uint(fmaxf(c0,c1)));
            }
        }
    }
    __syncthreads();
    for(int i=t;i<2400;i+=256){
        int n=i>>5, o=i&31;
        const float* ar=&acc[n*25];
        float s=0.f;
#pragma unroll
        for(int k=0;k<25;k++) s+=ar[k]*W1s[k*32+o];
        s=s/fmaxf(deg[n],1.f)+xin[n]*r1s[o]+b1s[o];
        atomicMax(&px[cl[n]*32+o], encf(eluf(s)));
    }
    __syncthreads();
    for(int i=t;i<1152;i+=256){
        int s=i>>5, f=i&31;
        float c=cnt[s];
        float v=(c>0.f)? decf(px[i]) : 0.f;
        g_x2[(g*36+s)*32+f]=v;
        g_x2h[(g*36+s)*32+f]=__float2bfloat16(v);
        if(f==0){
            g_cnt1[g*36+s]=c;
            g_ppos1[(g*36+s)*2]=ppx[s];
            g_ppos1[(g*36+s)*2+1]=ppy[s];
            g_deg2[g*36+s]=deg2s[s];
        }
    }
    if(t==0){ g_ecnt1[g]=ecnt; redMaxU(&g_amax[1],cmax); }
}

// ---------------- stage-2 gather: register accumulators, uniform switch on kb ----------------
#define CASE2(KB) case KB: acc[KB]+=wA*xv; acc[KB+1]+=wB*xv; acc[KB+5]+=wC*xv; acc[KB+6]+=wD*xv; break;
__global__ __launch_bounds__(512) void k_gather2(){
    __shared__ float xs[36*32];
    __shared__ float ppx[36], ppy[36], invd[36];
    __shared__ int offs[37], cursor[36];
    __shared__ __align__(8) uint2 pkw[1260];
    __shared__ unsigned short pka[1260];
    int g=blockIdx.x, t=threadIdx.x, lane=t&31, w=t>>5;
    for(int i=t;i<36*32;i+=512) xs[i]=g_x2[g*36*32+i];
    if(t<36){
        float d=g_deg2[g*36+t];
        ppx[t]=g_ppos1[(g*36+t)*2]; ppy[t]=g_ppos1[(g*36+t)*2+1];
        invd[t]=1.f/fmaxf(d,1.f);
        cursor[t]=(int)d;
    }
    __syncthreads();
    if(t==0){
        int a=0;
#pragma unroll
        for(int i=0;i<36;i++){ int c=cursor[i]; offs[i]=a; a+=c; }
        offs[36]=a;
    }
    __syncthreads();
    int ec=offs[36];
    if(t<36) cursor[t]=offs[t];
    __syncthreads();
    float amax=fmaxf(__uint_as_float(g_amax[1]),1e-12f);
    float inv=0.5f/amax;
    for(int i=t;i<ec;i+=512){
        unsigned r=g_el1[g*EPG+i];
        int a=r&255, b=(r>>8)&255;
        float p0=(ppx[a]-ppx[b])*inv+0.5f;
        float p1=(ppy[a]-ppy[b])*inv+0.5f;
        float v0=fminf(fmaxf(p0,0.f),1.f)*4.f;
        float v1=fminf(fmaxf(p1,0.f),1.f)*4.f;
        float b0=fminf(floorf(v0),3.f), b1f=fminf(floorf(v1),3.f);
        float f0=v0-b0, f1=v1-b1f;
        int kb=(int)b0+5*(int)b1f;
        int j=atomicAdd(&cursor[b],1);
        pkw[j]=make_uint2(packbf2w((1.f-f0)*(1.f-f1), f0*(1.f-f1)),
                          packbf2w((1.f-f0)*f1,       f0*f1));
        pka[j]=(unsigned short)((a<<5)|kb);
    }
    __syncthreads();
    for(int b=w;b<36;b+=16){
        float acc[25];
#pragma unroll
        for(int k=0;k<25;k++) acc[k]=0.f;
        int s0=offs[b], s1=offs[b+1];
        for(int j=s0;j<s1;j++){
            uint2 p=pkw[j];
            unsigned q=pka[j];
            int a=q>>5, kb=q&31;
            float xv=xs[a*32+lane];
            float wA=upperf(p.x), wB=lowerf(p.x), wC=upperf(p.y), wD=lowerf(p.y);
            switch(kb){
                CASE2(0) CASE2(1) CASE2(2) CASE2(3)
                CASE2(5) CASE2(6) CASE2(7) CASE2(8)
                CASE2(10) CASE2(11) CASE2(12) CASE2(13)
                CASE2(15) CASE2(16) CASE2(17) CASE2(18)
            }
        }
        float iv=invd[b];
#pragma unroll
        for(int k=0;k<25;k++){
            float v=acc[k]*iv;
            float nx=__shfl_down_sync(0xffffffffu,v,1);
            if(!(lane&1)){
                unsigned* po=(unsigned*)&g_acc2h[(size_t)(g*900+b*25+k)*32];
                po[lane>>1]=packbf(v,nx);
            }
        }
    }
}

// ---------------- bf16 tensor-core conv GEMM (128-row tile) ----------------
template<int KK,int FIN>
__global__ __launch_bounds__(256) void k_convB(
    const __nv_bfloat16* __restrict__ A, const __nv_bfloat16* __restrict__ Xh,
    const unsigned* __restrict__ Wp, const float* __restrict__ Bv,
    float* __restrict__ Out)
{
    constexpr int nTA=KK/32, nT=(KK+FIN)/32;
    __shared__ unsigned As2[16][136];
    __shared__ __align__(16) unsigned Ws2[16][72];
    int t=threadIdx.x, lane=t&31, w=t>>5;
    int gid=lane>>2, tig=lane&3;
    int n0=blockIdx.x*128;
    int m0=w*16;
    int r0=n0+m0+gid;
    float C[8][4];
#pragma unroll
    for(int j=0;j<8;j++){ C[j][0]=0.f; C[j][1]=0.f; C[j][2]=0.f; C[j][3]=0.f; }
    int ar=t>>1, half=t&1;
    int wkp=t>>4, wnb=(t&15)*4;
    uint4 pa0,pa1,pw;
    auto loadT=[&](int j){
        const __nv_bfloat16* Ap=(j<nTA)? A+(size_t)(n0+ar)*KK+j*32+half*16
                                       : Xh+(size_t)(n0+ar)*FIN+(j-nTA)*32+half*16;
        pa0=*(const uint4*)Ap;
        pa1=*(const uint4*)(Ap+8);
        pw =*(const uint4*)&Wp[(size_t)(j*16+wkp)*64+wnb];
    };
    loadT(0);
    for(int j=0;j<nT;j++){
        __syncthreads();
        int kb=half*8;
        As2[kb+0][ar]=pa0.x; As2[kb+1][ar]=pa0.y; As2[kb+2][ar]=pa0.z; As2[kb+3][ar]=pa0.w;
        As2[kb+4][ar]=pa1.x; As2[kb+5][ar]=pa1.y; As2[kb+6][ar]=pa1.z; As2[kb+7][ar]=pa1.w;
        *(uint4*)&Ws2[wkp][wnb]=pw;
        __syncthreads();
        if(j+1<nT) loadT(j+1);
#pragma unroll
        for(int s8=0;s8<16;s8+=8){
            unsigned a0=As2[s8+tig  ][m0+gid];
            unsigned a1=As2[s8+tig  ][m0+8+gid];
            unsigned a2=As2[s8+tig+4][m0+gid];
            unsigned a3=As2[s8+tig+4][m0+8+gid];
#pragma unroll
            for(int jj=0;jj<8;jj++){
                unsigned b0=Ws2[s8+tig  ][jj*8+gid];
                unsigned b1=Ws2[s8+tig+4][jj*8+gid];
                mma_bf16(C[jj],a0,a1,a2,a3,b0,b1);
            }
        }
    }
#pragma unroll
    for(int jj=0;jj<8;jj++){
        int c=jj*8+2*tig;
        float bv0=Bv[c], bv1=Bv[c+1];
        float2 o;
        o.x=eluf(C[jj][0]+bv0); o.y=eluf(C[jj][1]+bv1);
        *(float2*)&Out[(size_t)r0*64+c]=o;
        o.x=eluf(C[jj][2]+bv0); o.y=eluf(C[jj][3]+bv1);
        *(float2*)&Out[(size_t)(r0+8)*64+c]=o;
    }
}

// ---------------- pool2 + dedup2 fused (per graph) ----------------
__global__ __launch_bounds__(256) void k_pool2g(){
    int g=blockIdx.x, t=threadIdx.x;
    __shared__ unsigned px[25*64];
    __shared__ float cnt[25], psx[25], psy[25], ppx2[25], ppy2[25], deg3s[25];
    __shared__ unsigned char cl2[36], vld[36];
    __shared__ unsigned bm[20];
    __shared__ int ecnt;
    __shared__ unsigned cmax;
    for(int i=t;i<25*64;i+=256) px[i]=encf(-1e30f);
    if(t<25){ cnt[t]=0.f; psx[t]=0.f; psy[t]=0.f; deg3s[t]=0.f; }
    if(t>=32 && t<52) bm[t-32]=0u;
    if(t==0){ ecnt=0; cmax=0u; }
    __syncthreads();
    if(t<36){
        float qx=g_ppos1[(g*36+t)*2], qy=g_ppos1[(g*36+t)*2+1];
        int c0=min(max((int)floorf(qx/7.f),0),4);
        int c1=min(max((int)floorf(qy/7.f),0),4);
        int c=c1*5+c0;
        cl2[t]=(unsigned char)c;
        unsigned char v=(g_cnt1[g*36+t]>0.f)?1:0;
        vld[t]=v;
        if(v){ atomicAdd(&cnt[c],1.f); atomicAdd(&psx[c],qx); atomicAdd(&psy[c],qy); }
    }
    __syncthreads();
    if(t<25){
        float ic=1.f/fmaxf(cnt[t],1.f);
        ppx2[t]=psx[t]*ic; ppy2[t]=psy[t]*ic;
    }
    __syncthreads();
    for(int i=t;i<36*64;i+=256){
        int s=i>>6, f=i&63;
        if(vld[s]) atomicMax(&px[cl2[s]*64+f], encf(g_x2o[(g*36+s)*64+f]));
    }
    int ec=g_ecnt1[g];
    for(int i=t;i<ec;i+=256){
        unsigned r=g_el1[g*EPG+i];
        int a=cl2[r&255], b=cl2[(r>>8)&255];
        if(a!=b){
            int key=a*25+b;
            unsigned bit=1u<<(key&31);
            if(!(atomicOr(&bm[key>>5],bit)&bit)){
                int idx=atomicAdd(&ecnt,1);
                g_el2[g*EPG+idx]=(unsigned)a|((unsigned)b<<8);
                atomicAdd(&deg3s[b],1.f);
                float c0=fabsf(ppx2[a]-ppx2[b]), c1=fabsf(ppy2[a]-ppy2[b]);
                atomicMax(&cmax,__float_as_uint(fmaxf(c0,c1)));
            }
        }
    }
    __syncthreads();
    for(int i=t;i<25*64;i+=256){
        int s=i>>6, f=i&63;
        float c=cnt[s];
        float v=(c>0.f)? decf(px[i]) : 0.f;
        g_x3[(g*25+s)*64+f]=v;
        g_x3h[(g*25+s)*64+f]=__float2bfloat16(v);
        if(f==0){
            g_cnt2[g*25+s]=c;
            g_ppos2[(g*25+s)*2]=ppx2[s];
            g_ppos2[(g*25+s)*2+1]=ppy2[s];
            g_deg3[g*25+s]=deg3s[s];
        }
    }
    if(t==0){ g_ecnt2[g]=ecnt; redMaxU(&g_amax[2],cmax); }
}

// ---------------- stage-3 gather: register accumulators, uniform switch on kb ----------------
#define CASE3(KB) case KB: \
    ac0[KB]+=wA*x0; ac1[KB]+=wA*x1; ac0[KB+1]+=wB*x0; ac1[KB+1]+=wB*x1; \
    ac0[KB+5]+=wC*x0; ac1[KB+5]+=wC*x1; ac0[KB+6]+=wD*x0; ac1[KB+6]+=wD*x1; break;
__global__ __launch_bounds__(512) void k_gather3(){
    __shared__ float xs[25*64];
    __shared__ float ppx[25], ppy[25], invd[25];
    __shared__ int offs[26], cursor[25];
    __shared__ __align__(8) uint2 pkw[600];
    __shared__ unsigned short pka[600];
    int g=blockIdx.x, t=threadIdx.x, lane=t&31, w=t>>5;
    for(int i=t;i<25*64;i+=512) xs[i]=g_x3[g*25*64+i];
    if(t<25){
        float d=g_deg3[g*25+t];
        ppx[t]=g_ppos2[(g*25+t)*2]; ppy[t]=g_ppos2[(g*25+t)*2+1];
        invd[t]=1.f/fmaxf(d,1.f);
        cursor[t]=(int)d;
    }
    __syncthreads();
    if(t==0){
        int a=0;
#pragma unroll
        for(int i=0;i<25;i++){ int c=cursor[i]; offs[i]=a; a+=c; }
        offs[25]=a;
    }
    __syncthreads();
    int ec=offs[25];
    if(t<25) cursor[t]=offs[t];
    __syncthreads();
    float amax=fmaxf(__uint_as_float(g_amax[2]),1e-12f);
    float inv=0.5f/amax;
    for(int i=t;i<ec;i+=512){
        unsigned r=g_el2[g*EPG+i];
        int a=r&255, b=(r>>8)&255;
        float p0=(ppx[a]-ppx[b])*inv+0.5f;
        float p1=(ppy[a]-ppy[b])*inv+0.5f;
        float v0=fminf(fmaxf(p0,0.f),1.f)*4.f;
        float v1=fminf(fmaxf(p1,0.f),1.f)*4.f;
        float b0=fminf(floorf(v0),3.f), b1f=fminf(floorf(v1),3.f);
        float f0=v0-b0, f1=v1-b1f;
        int kb=(int)b0+5*(int)b1f;
        int j=atomicAdd(&cursor[b],1);
        pkw[j]=make_uint2(packbf2w((1.f-f0)*(1.f-f1), f0*(1.f-f1)),
                          packbf2w((1.f-f0)*f1,       f0*f1));
        pka[j]=(unsigned short)((a<<5)|kb);
    }
    __syncthreads();
    for(int b=w;b<25;b+=16){
        float ac0[25], ac1[25];
#pragma unroll
        for(int k=0;k<25;k++){ ac0[k]=0.f; ac1[k]=0.f; }
        int s0=offs[b], s1=offs[b+1];
        for(int j=s0;j<s1;j++){
            uint2 p=pkw[j];
            unsigned q=pka[j];
            int a=q>>5, kb=q&31;
            float x0=xs[a*64+lane], x1=xs[a*64+32+lane];
            float wA=upperf(p.x), wB=lowerf(p.x), wC=upperf(p.y), wD=lowerf(p.y);
            switch(kb){
                CASE3(0) CASE3(1) CASE3(2) CASE3(3)
                CASE3(5) CASE3(6) CASE3(7) CASE3(8)
                CASE3(10) CASE3(11) CASE3(12) CASE3(13)
                CASE3(15) CASE3(16) CASE3(17) CASE3(18)
            }
        }
        float iv=invd[b];
#pragma unroll
        for(int k=0;k<25;k++){
            float v0=ac0[k]*iv, v1=ac1[k]*iv;
            float n0=__shfl_down_sync(0xffffffffu,v0,1);
            float n1=__shfl_down_sync(0xffffffffu,v1,1);
            if(!(lane&1)){
                unsigned* po=(unsigned*)&g_acc3h[(size_t)(g*625+b*25+k)*64];
                po[lane>>1]=packbf(v0,n0);
                po[16+(lane>>1)]=packbf(v1,n1);
            }
        }
    }
}

// ---------------- fused final pool + FC head (per graph) ----------------
__global__ __launch_bounds__(128) void k_headg(const float* __restrict__ fw1,
        const float* __restrict__ fb1, const float* __restrict__ fw2,
        const float* __restrict__ fb2, float* __restrict__ out){
    __shared__ unsigned enc4[4*64];
    __shared__ unsigned any[4];
    __shared__ float in[256];
    __shared__ float h[128];
    __shared__ float lg[10];
    __shared__ float lse;
    int g=blockIdx.x, t=threadIdx.x;
    for(int i=t;i<256;i+=128) enc4[i]=encf(-1e30f);
    if(t<4) any[t]=0u;
    __syncthreads();
    for(int i=t;i<25*64;i+=128){
        int n=i>>6, f=i&63;
        if(g_cnt2[g*25+n]>0.f){
            float qx=g_ppos2[(g*25+n)*2], qy=g_ppos2[(g*25+n)*2+1];
            int c0=min(max((int)floorf(qx/14.f),0),1);
            int c1=min(max((int)floorf(qy/14.f),0),1);
            int cell=c1*2+c0;
            atomicMax(&enc4[cell*64+f], encf(g_x3o[(g*25+n)*64+f]));
            if(f==0) atomicOr(&any[cell],1u);
        }
    }
    __syncthreads();
    for(int i=t;i<256;i+=128)
        in[i]=any[i>>6]? decf(enc4[i]) : 0.f;
    __syncthreads();
    float s=fb1[t];
    const float4* wr=(const float4*)(fw1+(size_t)t*256);
#pragma unroll 8
    for(int i=0;i<64;i++){
        float4 w=wr[i];
        const float4 v=*(const float4*)&in[i*4];
        s+=w.x*v.x+w.y*v.y+w.z*v.z+w.w*v.w;
    }
    h[t]=eluf(s);
    __syncthreads();
    if(t<10){
        float l=fb2[t];
        for(int i=0;i<128;i++) l+=h[i]*fw2[t*128+i];
        lg[t]=l;
    }
    __syncthreads();
    if(t==0){
        float m=lg[0];
        for(int i=1;i<10;i++) m=fmaxf(m,lg[i]);
        float ss=0.f;
        for(int i=0;i<10;i++) ss+=expf(lg[i]-m);
        lse=m+logf(ss);
    }
    __syncthreads();
    if(t<10) out[g*10+t]=lg[t]-lse;
}

// ---------------- launch ----------------
extern "C" void kernel_launch(void* const* d_in, const int* in_sizes, int n_in,
                              void* d_out, int out_size){
    const float* x   =(const float*)d_in[0];
    const float* pos =(const float*)d_in[1];
    const int*   src =(const int*)  d_in[2];
    const int*   dst =(const int*)  d_in[3];
    const float* W1  =(const float*)d_in[4];
    const float* r1  =(const float*)d_in[5];
    const float* b1  =(const float*)d_in[6];
    const float* W2  =(const float*)d_in[7];
    const float* r2  =(const float*)d_in[8];
    const float* b2  =(const float*)d_in[9];
    const float* W3  =(const float*)d_in[10];
    const float* r3  =(const float*)d_in[11];
    const float* b3  =(const float*)d_in[12];
    const float* fw1 =(const float*)d_in[13];
    const float* fb1 =(const float*)d_in[14];
    const float* fw2 =(const float*)d_in[15];
    const float* fb2 =(const float*)d_in[16];
    float* out=(float*)d_out;

    __nv_bfloat16 *pA2h,*pX2h,*pA3h,*pX3h;
    unsigned *pWp2,*pWp3;
    float *pX2o,*pX3o;
    cudaGetSymbolAddress((void**)&pA2h, g_acc2h);
    cudaGetSymbolAddress((void**)&pX2h, g_x2h);
    cudaGetSymbolAddress((void**)&pA3h, g_acc3h);
    cudaGetSymbolAddress((void**)&pX3h, g_x3h);
    cudaGetSymbolAddress((void**)&pWp2, g_Wp2);
    cudaGetSymbolAddress((void**)&pWp3, g_Wp3);
    cudaGetSymbolAddress((void**)&pX2o, g_x2o);
    cudaGetSymbolAddress((void**)&pX3o, g_x3o);

    k_prepW<<<(416*64+832*64+255)/256,256>>>(W2,r2,W3,r3);
    k_amax0g<<<BB,256>>>(pos,src,dst);
    k_stage1<<<BB,256>>>(x,pos,src,dst,W1,r1,b1);
    k_gather2<<<BB,512>>>();
    k_convB<800,32><<<S1C/128,256>>>(pA2h,pX2h,pWp2,b2,pX2o);
    k_pool2g<<<BB,256>>>();
    k_gather3<<<BB,512>>>();
    k_convB<1600,64><<<S2C/128,256>>>(pA3h,pX3h,pWp3,b3,pX3o);
    k_headg<<<BB,128>>>(fw1,fb1,fw2,fb2,out);
}

// round 13
// speedup vs baseline: 1.0612x; 1.0612x over previous
#include <cuda_runtime.h>
#include <cuda_bf16.h>

#define NN   76800
#define EE   1425408
#define BB   1024
#define EPG  1392
#define S1C  36864
#define S2C  25600

// ---------------- device scratch ----------------
__device__ float g_x2[S1C*32];
__device__ __nv_bfloat16 g_x2h[S1C*32];
__device__ float g_cnt1[S1C];
__device__ float g_ppos1[S1C*2];
__device__ unsigned g_el1[EE];
__device__ int   g_ecnt1[BB];
__device__ float g_deg2[S1C];
__device__ __nv_bfloat16 g_acc2h[S1C*25*32];
__device__ float g_x2o[S1C*64];
__device__ float g_x3[S2C*64];
__device__ __nv_bfloat16 g_x3h[S2C*64];
__device__ float g_cnt2[S2C];
__device__ float g_ppos2[S2C*2];
__device__ unsigned g_el2[EE];
__device__ int   g_ecnt2[BB];
__device__ float g_deg3[S2C];
__device__ __nv_bfloat16 g_acc3h[S2C*25*64];
__device__ float g_x3o[S2C*64];
__device__ unsigned g_amax[4];
__device__ unsigned g_Wp2[416*64];
__device__ unsigned g_Wp3[832*64];

// ---------------- helpers ----------------
__device__ __forceinline__ unsigned encf(float f){
    unsigned u=__float_as_uint(f);
    return (u&0x80000000u)? ~u : (u|0x80000000u);
}
__device__ __forceinline__ float decf(unsigned u){
    return (u&0x80000000u)? __uint_as_float(u&0x7FFFFFFFu) : __uint_as_float(~u);
}
__device__ __forceinline__ float eluf(float x){ return x>0.f ? x : expm1f(x); }
__device__ __forceinline__ void redMaxU(unsigned* p, unsigned v){
    asm volatile("red.global.max.u32 [%0], %1;" :: "l"(p), "r"(v) : "memory");
}
__device__ __forceinline__ unsigned packbf(float a, float b){
    __nv_bfloat162 h=__floats2bfloat162_rn(a,b);
    return *reinterpret_cast<unsigned*>(&h);
}
__device__ __forceinline__ unsigned packbf2w(float hi, float lo){
    unsigned h=(unsigned)__bfloat16_as_ushort(__float2bfloat16(hi));
    unsigned l=(unsigned)__bfloat16_as_ushort(__float2bfloat16(lo));
    return (h<<16)|l;
}
__device__ __forceinline__ float upperf(unsigned u){ return __uint_as_float(u&0xFFFF0000u); }
__device__ __forceinline__ float lowerf(unsigned u){ return __uint_as_float(u<<16); }
__device__ __forceinline__ void mma_bf16(float* d, unsigned a0,unsigned a1,unsigned a2,unsigned a3,
                                         unsigned b0, unsigned b1){
    asm("mma.sync.aligned.m16n8k16.row.col.f32.bf16.bf16.f32 "
        "{%0,%1,%2,%3}, {%4,%5,%6,%7}, {%8,%9}, {%0,%1,%2,%3};"
        : "+f"(d[0]),"+f"(d[1]),"+f"(d[2]),"+f"(d[3])
        : "r"(a0),"r"(a1),"r"(a2),"r"(a3),"r"(b0),"r"(b1));
}

// ---------------- pack weights + amax reset ----------------
__global__ void k_prepW(const float* __restrict__ W2, const float* __restrict__ r2,
                        const float* __restrict__ W3, const float* __restrict__ r3){
    int i=blockIdx.x*blockDim.x+threadIdx.x;
    if(i<4) g_amax[i]=0u;
    if(i<416*64){
        int kp=i>>6, n=i&63;
        float lo,hi;
        if(kp<400){ lo=W2[(2*kp)*64+n]; hi=W2[(2*kp+1)*64+n]; }
        else      { int q=kp-400; lo=r2[(2*q)*64+n]; hi=r2[(2*q+1)*64+n]; }
        g_Wp2[i]=packbf(lo,hi);
    }
    int j=i-416*64;
    if(j>=0 && j<832*64){
        int kp=j>>6, n=j&63;
        float lo,hi;
        if(kp<800){ lo=W3[(2*kp)*64+n]; hi=W3[(2*kp+1)*64+n]; }
        else      { int q=kp-800; lo=r3[(2*q)*64+n]; hi=r3[(2*q+1)*64+n]; }
        g_Wp3[j]=packbf(lo,hi);
    }
}

// ---------------- stage-1 global amax ----------------
__global__ void k_amax0g(const float* __restrict__ pos, const int* __restrict__ src,
                         const int* __restrict__ dst){
    int g=blockIdx.x, t=threadIdx.x;
    __shared__ unsigned wm[8];
    unsigned cand=0u;
    for(int i=t;i<EPG;i+=256){
        int e=g*EPG+i;
        int s=src[e], d=dst[e];
        float c0=fabsf(pos[2*s]-pos[2*d]);
        float c1=fabsf(pos[2*s+1]-pos[2*d+1]);
        cand=max(cand,__float_as_uint(fmaxf(c0,c1)));
    }
    unsigned m=__reduce_max_sync(0xffffffffu,cand);
    if((t&31)==0) wm[t>>5]=m;
    __syncthreads();
    if(t==0){
        unsigned mm=0;
        #pragma unroll
        for(int i=0;i<8;i++) mm=max(mm,wm[i]);
        redMaxU(&g_amax[0],mm);
    }
}

// ---------------- fused stage 1: scatter + conv1 + pool1 + dedup1 ----------------
__global__ __launch_bounds__(256) void k_stage1(const float* __restrict__ x,
        const float* __restrict__ pos, const int* __restrict__ src,
        const int* __restrict__ dst, const float* __restrict__ W1,
        const float* __restrict__ r1, const float* __restrict__ b1){
    int g=blockIdx.x, t=threadIdx.x;
    __shared__ float acc[75*25];
    __shared__ float deg[75];
    __shared__ float posx[75], posy[75], xin[75];
    __shared__ float W1s[800], r1s[32], b1s[32];
    __shared__ unsigned px[36*32];
    __shared__ float cnt[36], psx[36], psy[36], ppx[36], ppy[36], deg2s[36];
    __shared__ unsigned char cl[75];
    __shared__ unsigned bm[41];
    __shared__ int ecnt;
    __shared__ unsigned cmax;

    for(int i=t;i<1875;i+=256) acc[i]=0.f;
    for(int i=t;i<800;i+=256) W1s[i]=W1[i];
    if(t<75){
        deg[t]=0.f;
        float2 p=*(const float2*)&pos[(g*75+t)*2];
        posx[t]=p.x; posy[t]=p.y;
        xin[t]=x[g*75+t];
    }
    if(t>=96 && t<128){ r1s[t-96]=r1[t-96]; b1s[t-96]=b1[t-96]; }
    if(t>=128 && t<164){ int c=t-128; cnt[c]=0.f; psx[c]=0.f; psy[c]=0.f; deg2s[c]=0.f; }
    if(t>=164 && t<205) bm[t-164]=0u;
    if(t==0){ ecnt=0; cmax=0u; }
    for(int i=t;i<1152;i+=256) px[i]=encf(-1e30f);
    __syncthreads();
    if(t<75){
        int c0=min(max((int)floorf(posx[t]/5.f),0),5);
        int c1=min(max((int)floorf(posy[t]/5.f),0),5);
        int c=c1*6+c0;
        cl[t]=(unsigned char)c;
        atomicAdd(&cnt[c],1.f);
        atomicAdd(&psx[c],posx[t]);
        atomicAdd(&psy[c],posy[t]);
    }
    __syncthreads();
    if(t<36){
        float ic=1.f/fmaxf(cnt[t],1.f);
        ppx[t]=psx[t]*ic; ppy[t]=psy[t]*ic;
    }
    __syncthreads();
    float amax=fmaxf(__uint_as_float(g_amax[0]),1e-12f);
    float inv=0.5f/amax;
    for(int i=t;i<EPG;i+=256){
        int e=g*EPG+i;
        int s=src[e]-g*75, d=dst[e]-g*75;
        float p0=(posx[s]-posx[d])*inv+0.5f;
        float p1=(posy[s]-posy[d])*inv+0.5f;
        float v0=fminf(fmaxf(p0,0.f),1.f)*4.f;
        float v1=fminf(fmaxf(p1,0.f),1.f)*4.f;
        float b0=fminf(floorf(v0),3.f), b1f=fminf(floorf(v1),3.f);
        int i0=(int)b0, i1=(int)b1f;
        float f0=v0-b0, f1=v1-b1f;
        float xs=xin[s];
        float* base=&acc[d*25+i0+5*i1];
        atomicAdd(base,   (1.f-f0)*(1.f-f1)*xs);
        atomicAdd(base+1, f0*(1.f-f1)*xs);
        atomicAdd(base+5, (1.f-f0)*f1*xs);
        atomicAdd(base+6, f0*f1*xs);
        atomicAdd(&deg[d],1.f);
        int a=cl[s], b=cl[d];
        if(a!=b){
            int key=a*36+b;
            unsigned bit=1u<<(key&31);
            if(!(atomicOr(&bm[key>>5],bit)&bit)){
                int idx=atomicAdd(&ecnt,1);
                g_el1[g*EPG+idx]=(unsigned)a|((unsigned)b<<8);
                atomicAdd(&deg2s[b],1.f);
                float c0=fabsf(ppx[a]-ppx[b]), c1=fabsf(ppy[a]-ppy[b]);
                atomicMax(&cmax,__float_as_uint(fmaxf(c0,c1)));
            }
        }
    }
    __syncthreads();
    for(int i=t;i<2400;i+=256){
        int n=i>>5, o=i&31;
        const float* ar=&acc[n*25];
        float s=0.f;
#pragma unroll
        for(int k=0;k<25;k++) s+=ar[k]*W1s[k*32+o];
        s=s/fmaxf(deg[n],1.f)+xin[n]*r1s[o]+b1s[o];
        atomicMax(&px[cl[n]*32+o], encf(eluf(s)));
    }
    __syncthreads();
    for(int i=t;i<1152;i+=256){
        int s=i>>5, f=i&31;
        float c=cnt[s];
        float v=(c>0.f)? decf(px[i]) : 0.f;
        g_x2[(g*36+s)*32+f]=v;
        g_x2h[(g*36+s)*32+f]=__float2bfloat16(v);
        if(f==0){
            g_cnt1[g*36+s]=c;
            g_ppos1[(g*36+s)*2]=ppx[s];
            g_ppos1[(g*36+s)*2+1]=ppy[s];
            g_deg2[g*36+s]=deg2s[s];
        }
    }
    if(t==0){ g_ecnt1[g]=ecnt; redMaxU(&g_amax[1],cmax); }
}

// ---------------- stage-2 gather: 512 thr, dynamic smem (round-11 proven) ----------------
#define G2_PKW    0
#define G2_ACCS   (1260*8)
#define G2_XS     (G2_ACCS+16*800*4)
#define G2_PPX    (G2_XS+1152*4)
#define G2_PPY    (G2_PPX+36*4)
#define G2_INVD   (G2_PPY+36*4)
#define G2_OFFS   (G2_INVD+36*4)
#define G2_CUR    (G2_OFFS+37*4)
#define G2_PKA    (G2_CUR+36*4)
#define G2_BYTES  (G2_PKA+1260*2+8)
__global__ __launch_bounds__(512) void k_gather2(){
    extern __shared__ char dyn2[];
    uint2* pkw=(uint2*)(dyn2+G2_PKW);
    float* accS=(float*)(dyn2+G2_ACCS);
    float* xs=(float*)(dyn2+G2_XS);
    float* ppx=(float*)(dyn2+G2_PPX);
    float* ppy=(float*)(dyn2+G2_PPY);
    float* invd=(float*)(dyn2+G2_INVD);
    int* offs=(int*)(dyn2+G2_OFFS);
    int* cursor=(int*)(dyn2+G2_CUR);
    unsigned short* pka=(unsigned short*)(dyn2+G2_PKA);
    int g=blockIdx.x, t=threadIdx.x, lane=t&31, w=t>>5;
    for(int i=t;i<36*32;i+=512) xs[i]=g_x2[g*36*32+i];
    if(t<36){
        float d=g_deg2[g*36+t];
        ppx[t]=g_ppos1[(g*36+t)*2]; ppy[t]=g_ppos1[(g*36+t)*2+1];
        invd[t]=1.f/fmaxf(d,1.f);
        cursor[t]=(int)d;
    }
    __syncthreads();
    if(t==0){
        int a=0;
#pragma unroll
        for(int i=0;i<36;i++){ int c=cursor[i]; offs[i]=a; a+=c; }
        offs[36]=a;
    }
    __syncthreads();
    int ec=offs[36];
    if(t<36) cursor[t]=offs[t];
    __syncthreads();
    float amax=fmaxf(__uint_as_float(g_amax[1]),1e-12f);
    float inv=0.5f/amax;
    for(int i=t;i<ec;i+=512){
        unsigned r=g_el1[g*EPG+i];
        int a=r&255, b=(r>>8)&255;
        float p0=(ppx[a]-ppx[b])*inv+0.5f;
        float p1=(ppy[a]-ppy[b])*inv+0.5f;
        float v0=fminf(fmaxf(p0,0.f),1.f)*4.f;
        float v1=fminf(fmaxf(p1,0.f),1.f)*4.f;
        float b0=fminf(floorf(v0),3.f), b1f=fminf(floorf(v1),3.f);
        float f0=v0-b0, f1=v1-b1f;
        int kb=(int)b0+5*(int)b1f;
        int j=atomicAdd(&cursor[b],1);
        pkw[j]=make_uint2(packbf2w((1.f-f0)*(1.f-f1), f0*(1.f-f1)),
                          packbf2w((1.f-f0)*f1,       f0*f1));
        pka[j]=(unsigned short)((a<<5)|kb);
    }
    __syncthreads();
    float* ac=&accS[w*800];
    for(int b=w;b<36;b+=16){
#pragma unroll
        for(int k=0;k<25;k++) ac[k*32+lane]=0.f;
        int s0=offs[b], s1=offs[b+1];
        for(int j=s0;j<s1;j++){
            uint2 p=pkw[j];
            unsigned q=pka[j];
            int a=q>>5, kb=q&31;
            float xv=xs[a*32+lane];
            float* pb=&ac[kb*32+lane];
            pb[0]    +=upperf(p.x)*xv;
            pb[32]   +=lowerf(p.x)*xv;
            pb[5*32] +=upperf(p.y)*xv;
            pb[6*32] +=lowerf(p.y)*xv;
        }
        float iv=invd[b];
#pragma unroll
        for(int k=0;k<25;k++){
            float v=ac[k*32+lane]*iv;
            float nx=__shfl_down_sync(0xffffffffu,v,1);
            if(!(lane&1)){
                unsigned* po=(unsigned*)&g_acc2h[(size_t)(g*900+b*25+k)*32];
                po[lane>>1]=packbf(v,nx);
            }
        }
    }
}

// ---------------- bf16 tensor-core conv GEMM (128-row tile, double-buffered) ----------------
template<int KK,int FIN>
__global__ __launch_bounds__(256) void k_convB(
    const __nv_bfloat16* __restrict__ A, const __nv_bfloat16* __restrict__ Xh,
    const unsigned* __restrict__ Wp, const float* __restrict__ Bv,
    float* __restrict__ Out)
{
    constexpr int nTA=KK/32, nT=(KK+FIN)/32;
    __shared__ unsigned As2[2][16][136];
    __shared__ __align__(16) unsigned Ws2[2][16][72];
    int t=threadIdx.x, lane=t&31, w=t>>5;
    int gid=lane>>2, tig=lane&3;
    int n0=blockIdx.x*128;
    int m0=w*16;
    int r0=n0+m0+gid;
    float C[8][4];
#pragma unroll
    for(int j=0;j<8;j++){ C[j][0]=0.f; C[j][1]=0.f; C[j][2]=0.f; C[j][3]=0.f; }
    int ar=t>>1, half=t&1;
    int wkp=t>>4, wnb=(t&15)*4;
    uint4 pa0,pa1,pw;
    auto loadT=[&](int j){
        const __nv_bfloat16* Ap=(j<nTA)? A+(size_t)(n0+ar)*KK+j*32+half*16
                                       : Xh+(size_t)(n0+ar)*FIN+(j-nTA)*32+half*16;
        pa0=*(const uint4*)Ap;
        pa1=*(const uint4*)(Ap+8);
        pw =*(const uint4*)&Wp[(size_t)(j*16+wkp)*64+wnb];
    };
    auto storeT=[&](int buf){
        int kb=half*8;
        As2[buf][kb+0][ar]=pa0.x; As2[buf][kb+1][ar]=pa0.y;
        As2[buf][kb+2][ar]=pa0.z; As2[buf][kb+3][ar]=pa0.w;
        As2[buf][kb+4][ar]=pa1.x; As2[buf][kb+5][ar]=pa1.y;
        As2[buf][kb+6][ar]=pa1.z; As2[buf][kb+7][ar]=pa1.w;
        *(uint4*)&Ws2[buf][wkp][wnb]=pw;
    };
    loadT(0);
    storeT(0);
    __syncthreads();
    for(int j=0;j<nT;j++){
        int cur=j&1;
        if(j+1<nT) loadT(j+1);
#pragma unroll
        for(int s8=0;s8<16;s8+=8){
            unsigned a0=As2[cur][s8+tig  ][m0+gid];
            unsigned a1=As2[cur][s8+tig  ][m0+8+gid];
            unsigned a2=As2[cur][s8+tig+4][m0+gid];
            unsigned a3=As2[cur][s8+tig+4][m0+8+gid];
#pragma unroll
            for(int jj=0;jj<8;jj++){
                unsigned b0=Ws2[cur][s8+tig  ][jj*8+gid];
                unsigned b1=Ws2[cur][s8+tig+4][jj*8+gid];
                mma_bf16(C[jj],a0,a1,a2,a3,b0,b1);
            }
        }
        if(j+1<nT){
            storeT((j+1)&1);
            __syncthreads();
        }
    }
#pragma unroll
    for(int jj=0;jj<8;jj++){
        int c=jj*8+2*tig;
        float bv0=Bv[c], bv1=Bv[c+1];
        float2 o;
        o.x=eluf(C[jj][0]+bv0); o.y=eluf(C[jj][1]+bv1);
        *(float2*)&Out[(size_t)r0*64+c]=o;
        o.x=eluf(C[jj][2]+bv0); o.y=eluf(C[jj][3]+bv1);
        *(float2*)&Out[(size_t)(r0+8)*64+c]=o;
    }
}

// ---------------- pool2 + dedup2 fused (per graph) ----------------
__global__ __launch_bounds__(256) void k_pool2g(){
    int g=blockIdx.x, t=threadIdx.x;
    __shared__ unsigned px[25*64];
    __shared__ float cnt[25], psx[25], psy[25], ppx2[25], ppy2[25], deg3s[25];
    __shared__ unsigned char cl2[36], vld[36];
    __shared__ unsigned bm[20];
    __shared__ int ecnt;
    __shared__ unsigned cmax;
    for(int i=t;i<25*64;i+=256) px[i]=encf(-1e30f);
    if(t<25){ cnt[t]=0.f; psx[t]=0.f; psy[t]=0.f; deg3s[t]=0.f; }
    if(t>=32 && t<52) bm[t-32]=0u;
    if(t==0){ ecnt=0; cmax=0u; }
    __syncthreads();
    if(t<36){
        float qx=g_ppos1[(g*36+t)*2], qy=g_ppos1[(g*36+t)*2+1];
        int c0=min(max((int)floorf(qx/7.f),0),4);
        int c1=min(max((int)floorf(qy/7.f),0),4);
        int c=c1*5+c0;
        cl2[t]=(unsigned char)c;
        unsigned char v=(g_cnt1[g*36+t]>0.f)?1:0;
        vld[t]=v;
        if(v){ atomicAdd(&cnt[c],1.f); atomicAdd(&psx[c],qx); atomicAdd(&psy[c],qy); }
    }
    __syncthreads();
    if(t<25){
        float ic=1.f/fmaxf(cnt[t],1.f);
        ppx2[t]=psx[t]*ic; ppy2[t]=psy[t]*ic;
    }
    __syncthreads();
    for(int i=t;i<36*64;i+=256){
        int s=i>>6, f=i&63;
        if(vld[s]) atomicMax(&px[cl2[s]*64+f], encf(g_x2o[(g*36+s)*64+f]));
    }
    int ec=g_ecnt1[g];
    for(int i=t;i<ec;i+=256){
        unsigned r=g_el1[g*EPG+i];
        int a=cl2[r&255], b=cl2[(r>>8)&255];
        if(a!=b){
            int key=a*25+b;
            unsigned bit=1u<<(key&31);
            if(!(atomicOr(&bm[key>>5],bit)&bit)){
                int idx=atomicAdd(&ecnt,1);
                g_el2[g*EPG+idx]=(unsigned)a|((unsigned)b<<8);
                atomicAdd(&deg3s[b],1.f);
                float c0=fabsf(ppx2[a]-ppx2[b]), c1=fabsf(ppy2[a]-ppy2[b]);
                atomicMax(&cmax,__float_as_uint(fmaxf(c0,c1)));
            }
        }
    }
    __syncthreads();
    for(int i=t;i<25*64;i+=256){
        int s=i>>6, f=i&63;
        float c=cnt[s];
        float v=(c>0.f)? decf(px[i]) : 0.f;
        g_x3[(g*25+s)*64+f]=v;
        g_x3h[(g*25+s)*64+f]=__float2bfloat16(v);
        if(f==0){
            g_cnt2[g*25+s]=c;
            g_ppos2[(g*25+s)*2]=ppx2[s];
            g_ppos2[(g*25+s)*2+1]=ppy2[s];
            g_deg3[g*25+s]=deg3s[s];
        }
    }
    if(t==0){ g_ecnt2[g]=ecnt; redMaxU(&g_amax[2],cmax); }
}

// ---------------- stage-3 gather: 384 thr, dynamic smem (round-11 proven) ----------------
#define G3_PKW    0
#define G3_ACCS   (600*8)
#define G3_XS     (G3_ACCS+12*1600*4)
#define G3_PPX    (G3_XS+1600*4)
#define G3_PPY    (G3_PPX+25*4)
#define G3_INVD   (G3_PPY+25*4)
#define G3_OFFS   (G3_INVD+25*4)
#define G3_CUR    (G3_OFFS+26*4)
#define G3_PKA    (G3_CUR+25*4)
#define G3_BYTES  (G3_PKA+600*2+8)
__global__ __launch_bounds__(384) void k_gather3(){
    extern __shared__ char dyn3[];
    uint2* pkw=(uint2*)(dyn3+G3_PKW);
    float* accS=(float*)(dyn3+G3_ACCS);
    float* xs=(float*)(dyn3+G3_XS);
    float* ppx=(float*)(dyn3+G3_PPX);
    float* ppy=(float*)(dyn3+G3_PPY);
    float* invd=(float*)(dyn3+G3_INVD);
    int* offs=(int*)(dyn3+G3_OFFS);
    int* cursor=(int*)(dyn3+G3_CUR);
    unsigned short* pka=(unsigned short*)(dyn3+G3_PKA);
    int g=blockIdx.x, t=threadIdx.x, lane=t&31, w=t>>5;
    for(int i=t;i<25*64;i+=384) xs[i]=g_x3[g*25*64+i];
    if(t<25){
        float d=g_deg3[g*25+t];
        ppx[t]=g_ppos2[(g*25+t)*2]; ppy[t]=g_ppos2[(g*25+t)*2+1];
        invd[t]=1.f/fmaxf(d,1.f);
        cursor[t]=(int)d;
    }
    __syncthreads();
    if(t==0){
        int a=0;
#pragma unroll
        for(int i=0;i<25;i++){ int c=cursor[i]; offs[i]=a; a+=c; }
        offs[25]=a;
    }
    __syncthreads();
    int ec=offs[25];
    if(t<25) cursor[t]=offs[t];
    __syncthreads();
    float amax=fmaxf(__uint_as_float(g_amax[2]),1e-12f);
    float inv=0.5f/amax;
    for(int i=t;i<ec;i+=384){
        unsigned r=g_el2[g*EPG+i];
        int a=r&255, b=(r>>8)&255;
        float p0=(ppx[a]-ppx[b])*inv+0.5f;
        float p1=(ppy[a]-ppy[b])*inv+0.5f;
        float v0=fminf(fmaxf(p0,0.f),1.f)*4.f;
        float v1=fminf(fmaxf(p1,0.f),1.f)*4.f;
        float b0=fminf(floorf(v0),3.f), b1f=fminf(floorf(v1),3.f);
        float f0=v0-b0, f1=v1-b1f;
        int kb=(int)b0+5*(int)b1f;
        int j=atomicAdd(&cursor[b],1);
        pkw[j]=make_uint2(packbf2w((1.f-f0)*(1.f-f1), f0*(1.f-f1)),
                          packbf2w((1.f-f0)*f1,       f0*f1));
        pka[j]=(unsigned short)((a<<5)|kb);
    }
    __syncthreads();
    float* ac=&accS[w*1600];
    for(int b=w;b<25;b+=12){
#pragma unroll
        for(int k=0;k<25;k++){ ac[k*64+lane]=0.f; ac[k*64+32+lane]=0.f; }
        int s0=offs[b], s1=offs[b+1];
        for(int j=s0;j<s1;j++){
            uint2 p=pkw[j];
            unsigned q=pka[j];
            int a=q>>5, kb=q&31;
            float x0=xs[a*64+lane], x1=xs[a*64+32+lane];
            float wA=upperf(p.x), wB=lowerf(p.x), wC=upperf(p.y), wD=lowerf(p.y);
            float* pb=&ac[kb*64+lane];
            pb[0]      +=wA*x0; pb[32]     +=wA*x1;
            pb[64]     +=wB*x0; pb[96]     +=wB*x1;
            pb[5*64]   +=wC*x0; pb[5*64+32]+=wC*x1;
            pb[6*64]   +=wD*x0; pb[6*64+32]+=wD*x1;
        }
        float iv=invd[b];
#pragma unroll
        for(int k=0;k<25;k++){
            float v0=ac[k*64+lane]*iv, v1=ac[k*64+32+lane]*iv;
            float n0=__shfl_down_sync(0xffffffffu,v0,1);
            float n1=__shfl_down_sync(0xffffffffu,v1,1);
            if(!(lane&1)){
                unsigned* po=(unsigned*)&g_acc3h[(size_t)(g*625+b*25+k)*64];
                po[lane>>1]=packbf(v0,n0);
                po[16+(lane>>1)]=packbf(v1,n1);
            }
        }
    }
}

// ---------------- fused final pool + FC head (per graph) ----------------
__global__ __launch_bounds__(128) void k_headg(const float* __restrict__ fw1,
        const float* __restrict__ fb1, const float* __restrict__ fw2,
        const float* __restrict__ fb2, float* __restrict__ out){
    __shared__ unsigned enc4[4*64];
    __shared__ unsigned any[4];
    __shared__ float in[256];
    __shared__ float h[128];
    __shared__ float lg[10];
    __shared__ float lse;
    int g=blockIdx.x, t=threadIdx.x;
    for(int i=t;i<256;i+=128) enc4[i]=encf(-1e30f);
    if(t<4) any[t]=0u;
    __syncthreads();
    for(int i=t;i<25*64;i+=128){
        int n=i>>6, f=i&63;
        if(g_cnt2[g*25+n]>0.f){
            float qx=g_ppos2[(g*25+n)*2], qy=g_ppos2[(g*25+n)*2+1];
            int c0=min(max((int)floorf(qx/14.f),0),1);
            int c1=min(max((int)floorf(qy/14.f),0),1);
            int cell=c1*2+c0;
            atomicMax(&enc4[cell*64+f], encf(g_x3o[(g*25+n)*64+f]));
            if(f==0) atomicOr(&any[cell],1u);
        }
    }
    __syncthreads();
    for(int i=t;i<256;i+=128)
        in[i]=any[i>>6]? decf(enc4[i]) : 0.f;
    __syncthreads();
    float s=fb1[t];
    const float4* wr=(const float4*)(fw1+(size_t)t*256);
#pragma unroll 8
    for(int i=0;i<64;i++){
        float4 w=wr[i];
        const float4 v=*(const float4*)&in[i*4];
        s+=w.x*v.x+w.y*v.y+w.z*v.z+w.w*v.w;
    }
    h[t]=eluf(s);
    __syncthreads();
    if(t<10){
        float l=fb2[t];
        for(int i=0;i<128;i++) l+=h[i]*fw2[t*128+i];
        lg[t]=l;
    }
    __syncthreads();
    if(t==0){
        float m=lg[0];
        for(int i=1;i<10;i++) m=fmaxf(m,lg[i]);
        float ss=0.f;
        for(int i=0;i<10;i++) ss+=expf(lg[i]-m);
        lse=m+logf(ss);
    }
    __syncthreads();
    if(t<10) out[g*10+t]=lg[t]-lse;
}

// ---------------- launch ----------------
extern "C" void kernel_launch(void* const* d_in, const int* in_sizes, int n_in,
                              void* d_out, int out_size){
    const float* x   =(const float*)d_in[0];
    const float* pos =(const float*)d_in[1];
    const int*   src =(const int*)  d_in[2];
    const int*   dst =(const int*)  d_in[3];
    const float* W1  =(const float*)d_in[4];
    const float* r1  =(const float*)d_in[5];
    const float* b1  =(const float*)d_in[6];
    const float* W2  =(const float*)d_in[7];
    const float* r2  =(const float*)d_in[8];
    const float* b2  =(const float*)d_in[9];
    const float* W3  =(const float*)d_in[10];
    const float* r3  =(const float*)d_in[11];
    const float* b3  =(const float*)d_in[12];
    const float* fw1 =(const float*)d_in[13];
    const float* fb1 =(const float*)d_in[14];
    const float* fw2 =(const float*)d_in[15];
    const float* fb2 =(const float*)d_in[16];
    float* out=(float*)d_out;

    __nv_bfloat16 *pA2h,*pX2h,*pA3h,*pX3h;
    unsigned *pWp2,*pWp3;
    float *pX2o,*pX3o;
    cudaGetSymbolAddress((void**)&pA2h, g_acc2h);
    cudaGetSymbolAddress((void**)&pX2h, g_x2h);
    cudaGetSymbolAddress((void**)&pA3h, g_acc3h);
    cudaGetSymbolAddress((void**)&pX3h, g_x3h);
    cudaGetSymbolAddress((void**)&pWp2, g_Wp2);
    cudaGetSymbolAddress((void**)&pWp3, g_Wp3);
    cudaGetSymbolAddress((void**)&pX2o, g_x2o);
    cudaGetSymbolAddress((void**)&pX3o, g_x3o);

    static int attrdone=0;
    if(!attrdone){
        cudaFuncSetAttribute(k_gather2, cudaFuncAttributeMaxDynamicSharedMemorySize, G2_BYTES);
        cudaFuncSetAttribute(k_gather3, cudaFuncAttributeMaxDynamicSharedMemorySize, G3_BYTES);
        attrdone=1;
    }

    k_prepW<<<(416*64+832*64+255)/256,256>>>(W2,r2,W3,r3);
    k_amax0g<<<BB,256>>>(pos,src,dst);
    k_stage1<<<BB,256>>>(x,pos,src,dst,W1,r1,b1);
    k_gather2<<<BB,512,G2_BYTES>>>();
    k_convB<800,32><<<S1C/128,256>>>(pA2h,pX2h,pWp2,b2,pX2o);
    k_pool2g<<<BB,256>>>();
    k_gather3<<<BB,384,G3_BYTES>>>();
    k_convB<1600,64><<<S2C/128,256>>>(pA3h,pX3h,pWp3,b3,pX3o);
    k_headg<<<BB,128>>>(fw1,fb1,fw2,fb2,out);
}

// round 14
// speedup vs baseline: 1.0623x; 1.0010x over previous
#include <cuda_runtime.h>
#include <cuda_bf16.h>

#define NN   76800
#define EE   1425408
#define BB   1024
#define EPG  1392
#define S1C  36864
#define S2C  25600

// ---------------- device scratch ----------------
__device__ float g_x2[S1C*32];
__device__ __nv_bfloat16 g_x2h[S1C*32];
__device__ float g_cnt1[S1C];
__device__ float g_ppos1[S1C*2];
__device__ unsigned g_el1[EE];
__device__ int   g_ecnt1[BB];
__device__ float g_deg2[S1C];
__device__ __nv_bfloat16 g_acc2h[S1C*25*32];
__device__ float g_x2o[S1C*64];
__device__ float g_x3[S2C*64];
__device__ __nv_bfloat16 g_x3h[S2C*64];
__device__ float g_cnt2[S2C];
__device__ float g_ppos2[S2C*2];
__device__ unsigned g_el2[EE];
__device__ int   g_ecnt2[BB];
__device__ float g_deg3[S2C];
__device__ __nv_bfloat16 g_acc3h[S2C*25*64];
__device__ float g_x3o[S2C*64];
__device__ unsigned g_amax[4];
__device__ unsigned g_Wp2[416*64];
__device__ unsigned g_Wp3[832*64];

// ---------------- helpers ----------------
__device__ __forceinline__ unsigned encf(float f){
    unsigned u=__float_as_uint(f);
    return (u&0x80000000u)? ~u : (u|0x80000000u);
}
__device__ __forceinline__ float decf(unsigned u){
    return (u&0x80000000u)? __uint_as_float(u&0x7FFFFFFFu) : __uint_as_float(~u);
}
__device__ __forceinline__ float eluf(float x){ return x>0.f ? x : expm1f(x); }
__device__ __forceinline__ void redMaxU(unsigned* p, unsigned v){
    asm volatile("red.global.max.u32 [%0], %1;" :: "l"(p), "r"(v) : "memory");
}
__device__ __forceinline__ unsigned packbf(float a, float b){
    __nv_bfloat162 h=__floats2bfloat162_rn(a,b);
    return *reinterpret_cast<unsigned*>(&h);
}
__device__ __forceinline__ unsigned packbf2w(float hi, float lo){
    unsigned h=(unsigned)__bfloat16_as_ushort(__float2bfloat16(hi));
    unsigned l=(unsigned)__bfloat16_as_ushort(__float2bfloat16(lo));
    return (h<<16)|l;
}
__device__ __forceinline__ float upperf(unsigned u){ return __uint_as_float(u&0xFFFF0000u); }
__device__ __forceinline__ float lowerf(unsigned u){ return __uint_as_float(u<<16); }
__device__ __forceinline__ void mma_bf16(float* d, unsigned a0,unsigned a1,unsigned a2,unsigned a3,
                                         unsigned b0, unsigned b1){
    asm("mma.sync.aligned.m16n8k16.row.col.f32.bf16.bf16.f32 "
        "{%0,%1,%2,%3}, {%4,%5,%6,%7}, {%8,%9}, {%0,%1,%2,%3};"
        : "+f"(d[0]),"+f"(d[1]),"+f"(d[2]),"+f"(d[3])
        : "r"(a0),"r"(a1),"r"(a2),"r"(a3),"r"(b0),"r"(b1));
}

// ---------------- fused prep: per-graph amax (blocks 0..1023) + weight pack ----------------
__global__ void k_prep(const float* __restrict__ pos, const int* __restrict__ src,
                       const int* __restrict__ dst,
                       const float* __restrict__ W2, const float* __restrict__ r2,
                       const float* __restrict__ W3, const float* __restrict__ r3){
    int blk=blockIdx.x, t=threadIdx.x;
    if(blk<BB){
        __shared__ unsigned wm[8];
        int g=blk;
        unsigned cand=0u;
        for(int i=t;i<EPG;i+=256){
            int e=g*EPG+i;
            int s=src[e], d=dst[e];
            float c0=fabsf(pos[2*s]-pos[2*d]);
            float c1=fabsf(pos[2*s+1]-pos[2*d+1]);
            cand=max(cand,__float_as_uint(fmaxf(c0,c1)));
        }
        unsigned m=__reduce_max_sync(0xffffffffu,cand);
        if((t&31)==0) wm[t>>5]=m;
        __syncthreads();
        if(t==0){
            unsigned mm=0;
#pragma unroll
            for(int i=0;i<8;i++) mm=max(mm,wm[i]);
            redMaxU(&g_amax[0],mm);
        }
        return;
    }
    int i=(blk-BB)*256+t;
    if(i<4) g_amax[1+((i<3)?i:2)]=g_amax[1+((i<3)?i:2)]; // no-op filler
    if(i<416*64){
        int kp=i>>6, n=i&63;
        float lo,hi;
        if(kp<400){ lo=W2[(2*kp)*64+n]; hi=W2[(2*kp+1)*64+n]; }
        else      { int q=kp-400; lo=r2[(2*q)*64+n]; hi=r2[(2*q+1)*64+n]; }
        g_Wp2[i]=packbf(lo,hi);
    }
    int j=i-416*64;
    if(j>=0 && j<832*64){
        int kp=j>>6, n=j&63;
        float lo,hi;
        if(kp<800){ lo=W3[(2*kp)*64+n]; hi=W3[(2*kp+1)*64+n]; }
        else      { int q=kp-800; lo=r3[(2*q)*64+n]; hi=r3[(2*q+1)*64+n]; }
        g_Wp3[j]=packbf(lo,hi);
    }
}
__global__ void k_reset0(){ if(threadIdx.x<4) g_amax[threadIdx.x]=0u; }

// ---------------- fused stage 1 (512 threads): scatter + conv1 + pool1 + dedup1 ----------------
__global__ __launch_bounds__(512) void k_stage1(const float* __restrict__ x,
        const float* __restrict__ pos, const int* __restrict__ src,
        const int* __restrict__ dst, const float* __restrict__ W1,
        const float* __restrict__ r1, const float* __restrict__ b1){
    int g=blockIdx.x, t=threadIdx.x;
    __shared__ float acc[75*25];
    __shared__ float deg[75];
    __shared__ float posx[75], posy[75], xin[75];
    __shared__ float W1s[800], r1s[32], b1s[32];
    __shared__ unsigned px[36*32];
    __shared__ float cnt[36], psx[36], psy[36], ppx[36], ppy[36], deg2s[36];
    __shared__ unsigned char cl[75];
    __shared__ unsigned bm[41];
    __shared__ int ecnt;
    __shared__ unsigned cmax;

    for(int i=t;i<1875;i+=512) acc[i]=0.f;
    for(int i=t;i<800;i+=512) W1s[i]=W1[i];
    if(t<75){
        deg[t]=0.f;
        float2 p=*(const float2*)&pos[(g*75+t)*2];
        posx[t]=p.x; posy[t]=p.y;
        xin[t]=x[g*75+t];
    }
    if(t>=96 && t<128){ r1s[t-96]=r1[t-96]; b1s[t-96]=b1[t-96]; }
    if(t>=128 && t<164){ int c=t-128; cnt[c]=0.f; psx[c]=0.f; psy[c]=0.f; deg2s[c]=0.f; }
    if(t>=164 && t<205) bm[t-164]=0u;
    if(t==0){ ecnt=0; cmax=0u; }
    for(int i=t;i<1152;i+=512) px[i]=encf(-1e30f);
    __syncthreads();
    if(t<75){
        int c0=min(max((int)floorf(posx[t]/5.f),0),5);
        int c1=min(max((int)floorf(posy[t]/5.f),0),5);
        int c=c1*6+c0;
        cl[t]=(unsigned char)c;
        atomicAdd(&cnt[c],1.f);
        atomicAdd(&psx[c],posx[t]);
        atomicAdd(&psy[c],posy[t]);
    }
    __syncthreads();
    if(t<36){
        float ic=1.f/fmaxf(cnt[t],1.f);
        ppx[t]=psx[t]*ic; ppy[t]=psy[t]*ic;
    }
    __syncthreads();
    float amax=fmaxf(__uint_as_float(g_amax[0]),1e-12f);
    float inv=0.5f/amax;
    for(int i=t;i<EPG;i+=512){
        int e=g*EPG+i;
        int s=src[e]-g*75, d=dst[e]-g*75;
        float p0=(posx[s]-posx[d])*inv+0.5f;
        float p1=(posy[s]-posy[d])*inv+0.5f;
        float v0=fminf(fmaxf(p0,0.f),1.f)*4.f;
        float v1=fminf(fmaxf(p1,0.f),1.f)*4.f;
        float b0=fminf(floorf(v0),3.f), b1f=fminf(floorf(v1),3.f);
        int i0=(int)b0, i1=(int)b1f;
        float f0=v0-b0, f1=v1-b1f;
        float xs=xin[s];
        float* base=&acc[d*25+i0+5*i1];
        atomicAdd(base,   (1.f-f0)*(1.f-f1)*xs);
        atomicAdd(base+1, f0*(1.f-f1)*xs);
        atomicAdd(base+5, (1.f-f0)*f1*xs);
        atomicAdd(base+6, f0*f1*xs);
        atomicAdd(&deg[d],1.f);
        int a=cl[s], b=cl[d];
        if(a!=b){
            int key=a*36+b;
            unsigned bit=1u<<(key&31);
            if(!(atomicOr(&bm[key>>5],bit)&bit)){
                int idx=atomicAdd(&ecnt,1);
                g_el1[g*EPG+idx]=(unsigned)a|((unsigned)b<<8);
                atomicAdd(&deg2s[b],1.f);
                float c0=fabsf(ppx[a]-ppx[b]), c1=fabsf(ppy[a]-ppy[b]);
                atomicMax(&cmax,__float_as_uint(fmaxf(c0,c1)));
            }
        }
    }
    __syncthreads();
    for(int i=t;i<2400;i+=512){
        int n=i>>5, o=i&31;
        const float* ar=&acc[n*25];
        float s=0.f;
#pragma unroll
        for(int k=0;k<25;k++) s+=ar[k]*W1s[k*32+o];
        s=s/fmaxf(deg[n],1.f)+xin[n]*r1s[o]+b1s[o];
        atomicMax(&px[cl[n]*32+o], encf(eluf(s)));
    }
    __syncthreads();
    for(int i=t;i<1152;i+=512){
        int s=i>>5, f=i&31;
        float c=cnt[s];
        float v=(c>0.f)? decf(px[i]) : 0.f;
        g_x2[(g*36+s)*32+f]=v;
        g_x2h[(g*36+s)*32+f]=__float2bfloat16(v);
        if(f==0){
            g_cnt1[g*36+s]=c;
            g_ppos1[(g*36+s)*2]=ppx[s];
            g_ppos1[(g*36+s)*2+1]=ppy[s];
            g_deg2[g*36+s]=deg2s[s];
        }
    }
    if(t==0){ g_ecnt1[g]=ecnt; redMaxU(&g_amax[1],cmax); }
}

// ---------------- stage-2 gather: 512 thr, dynamic smem (round-11 proven) ----------------
#define G2_PKW    0
#define G2_ACCS   (1260*8)
#define G2_XS     (G2_ACCS+16*800*4)
#define G2_PPX    (G2_XS+1152*4)
#define G2_PPY    (G2_PPX+36*4)
#define G2_INVD   (G2_PPY+36*4)
#define G2_OFFS   (G2_INVD+36*4)
#define G2_CUR    (G2_OFFS+37*4)
#define G2_PKA    (G2_CUR+36*4)
#define G2_BYTES  (G2_PKA+1260*2+8)
__global__ __launch_bounds__(512) void k_gather2(){
    extern __shared__ char dyn2[];
    uint2* pkw=(uint2*)(dyn2+G2_PKW);
    float* accS=(float*)(dyn2+G2_ACCS);
    float* xs=(float*)(dyn2+G2_XS);
    float* ppx=(float*)(dyn2+G2_PPX);
    float* ppy=(float*)(dyn2+G2_PPY);
    float* invd=(float*)(dyn2+G2_INVD);
    int* offs=(int*)(dyn2+G2_OFFS);
    int* cursor=(int*)(dyn2+G2_CUR);
    unsigned short* pka=(unsigned short*)(dyn2+G2_PKA);
    int g=blockIdx.x, t=threadIdx.x, lane=t&31, w=t>>5;
    for(int i=t;i<36*32;i+=512) xs[i]=g_x2[g*36*32+i];
    if(t<36){
        float d=g_deg2[g*36+t];
        ppx[t]=g_ppos1[(g*36+t)*2]; ppy[t]=g_ppos1[(g*36+t)*2+1];
        invd[t]=1.f/fmaxf(d,1.f);
        cursor[t]=(int)d;
    }
    __syncthreads();
    if(t==0){
        int a=0;
#pragma unroll
        for(int i=0;i<36;i++){ int c=cursor[i]; offs[i]=a; a+=c; }
        offs[36]=a;
    }
    __syncthreads();
    int ec=offs[36];
    if(t<36) cursor[t]=offs[t];
    __syncthreads();
    float amax=fmaxf(__uint_as_float(g_amax[1]),1e-12f);
    float inv=0.5f/amax;
    for(int i=t;i<ec;i+=512){
        unsigned r=g_el1[g*EPG+i];
        int a=r&255, b=(r>>8)&255;
        float p0=(ppx[a]-ppx[b])*inv+0.5f;
        float p1=(ppy[a]-ppy[b])*inv+0.5f;
        float v0=fminf(fmaxf(p0,0.f),1.f)*4.f;
        float v1=fminf(fmaxf(p1,0.f),1.f)*4.f;
        float b0=fminf(floorf(v0),3.f), b1f=fminf(floorf(v1),3.f);
        float f0=v0-b0, f1=v1-b1f;
        int kb=(int)b0+5*(int)b1f;
        int j=atomicAdd(&cursor[b],1);
        pkw[j]=make_uint2(packbf2w((1.f-f0)*(1.f-f1), f0*(1.f-f1)),
                          packbf2w((1.f-f0)*f1,       f0*f1));
        pka[j]=(unsigned short)((a<<5)|kb);
    }
    __syncthreads();
    float* ac=&accS[w*800];
    for(int b=w;b<36;b+=16){
#pragma unroll
        for(int k=0;k<25;k++) ac[k*32+lane]=0.f;
        int s0=offs[b], s1=offs[b+1];
        for(int j=s0;j<s1;j++){
            uint2 p=pkw[j];
            unsigned q=pka[j];
            int a=q>>5, kb=q&31;
            float xv=xs[a*32+lane];
            float* pb=&ac[kb*32+lane];
            pb[0]    +=upperf(p.x)*xv;
            pb[32]   +=lowerf(p.x)*xv;
            pb[5*32] +=upperf(p.y)*xv;
            pb[6*32] +=lowerf(p.y)*xv;
        }
        float iv=invd[b];
#pragma unroll
        for(int k=0;k<25;k++){
            float v=ac[k*32+lane]*iv;
            float nx=__shfl_down_sync(0xffffffffu,v,1);
            if(!(lane&1)){
                unsigned* po=(unsigned*)&g_acc2h[(size_t)(g*900+b*25+k)*32];
                po[lane>>1]=packbf(v,nx);
            }
        }
    }
}

// ---------------- bf16 tensor-core conv GEMM (round-11 single-buffered 128-row tile) ----------------
template<int KK,int FIN>
__global__ __launch_bounds__(256) void k_convB(
    const __nv_bfloat16* __restrict__ A, const __nv_bfloat16* __restrict__ Xh,
    const unsigned* __restrict__ Wp, const float* __restrict__ Bv,
    float* __restrict__ Out)
{
    constexpr int nTA=KK/32, nT=(KK+FIN)/32;
    __shared__ unsigned As2[16][136];
    __shared__ __align__(16) unsigned Ws2[16][72];
    int t=threadIdx.x, lane=t&31, w=t>>5;
    int gid=lane>>2, tig=lane&3;
    int n0=blockIdx.x*128;
    int m0=w*16;
    int r0=n0+m0+gid;
    float C[8][4];
#pragma unroll
    for(int j=0;j<8;j++){ C[j][0]=0.f; C[j][1]=0.f; C[j][2]=0.f; C[j][3]=0.f; }
    int ar=t>>1, half=t&1;
    int wkp=t>>4, wnb=(t&15)*4;
    uint4 pa0,pa1,pw;
    auto loadT=[&](int j){
        const __nv_bfloat16* Ap=(j<nTA)? A+(size_t)(n0+ar)*KK+j*32+half*16
                                       : Xh+(size_t)(n0+ar)*FIN+(j-nTA)*32+half*16;
        pa0=*(const uint4*)Ap;
        pa1=*(const uint4*)(Ap+8);
        pw =*(const uint4*)&Wp[(size_t)(j*16+wkp)*64+wnb];
    };
    loadT(0);
    for(int j=0;j<nT;j++){
        __syncthreads();
        int kb=half*8;
        As2[kb+0][ar]=pa0.x; As2[kb+1][ar]=pa0.y; As2[kb+2][ar]=pa0.z; As2[kb+3][ar]=pa0.w;
        As2[kb+4][ar]=pa1.x; As2[kb+5][ar]=pa1.y; As2[kb+6][ar]=pa1.z; As2[kb+7][ar]=pa1.w;
        *(uint4*)&Ws2[wkp][wnb]=pw;
        __syncthreads();
        if(j+1<nT) loadT(j+1);
#pragma unroll
        for(int s8=0;s8<16;s8+=8){
            unsigned a0=As2[s8+tig  ][m0+gid];
            unsigned a1=As2[s8+tig  ][m0+8+gid];
            unsigned a2=As2[s8+tig+4][m0+gid];
            unsigned a3=As2[s8+tig+4][m0+8+gid];
#pragma unroll
            for(int jj=0;jj<8;jj++){
                unsigned b0=Ws2[s8+tig  ][jj*8+gid];
                unsigned b1=Ws2[s8+tig+4][jj*8+gid];
                mma_bf16(C[jj],a0,a1,a2,a3,b0,b1);
            }
        }
    }
#pragma unroll
    for(int jj=0;jj<8;jj++){
        int c=jj*8+2*tig;
        float bv0=Bv[c], bv1=Bv[c+1];
        float2 o;
        o.x=eluf(C[jj][0]+bv0); o.y=eluf(C[jj][1]+bv1);
        *(float2*)&Out[(size_t)r0*64+c]=o;
        o.x=eluf(C[jj][2]+bv0); o.y=eluf(C[jj][3]+bv1);
        *(float2*)&Out[(size_t)(r0+8)*64+c]=o;
    }
}

// ---------------- pool2 + dedup2 fused (per graph) ----------------
__global__ __launch_bounds__(256) void k_pool2g(){
    int g=blockIdx.x, t=threadIdx.x;
    __shared__ unsigned px[25*64];
    __shared__ float cnt[25], psx[25], psy[25], ppx2[25], ppy2[25], deg3s[25];
    __shared__ unsigned char cl2[36], vld[36];
    __shared__ unsigned bm[20];
    __shared__ int ecnt;
    __shared__ unsigned cmax;
    for(int i=t;i<25*64;i+=256) px[i]=encf(-1e30f);
    if(t<25){ cnt[t]=0.f; psx[t]=0.f; psy[t]=0.f; deg3s[t]=0.f; }
    if(t>=32 && t<52) bm[t-32]=0u;
    if(t==0){ ecnt=0; cmax=0u; }
    __syncthreads();
    if(t<36){
        float qx=g_ppos1[(g*36+t)*2], qy=g_ppos1[(g*36+t)*2+1];
        int c0=min(max((int)floorf(qx/7.f),0),4);
        int c1=min(max((int)floorf(qy/7.f),0),4);
        int c=c1*5+c0;
        cl2[t]=(unsigned char)c;
        unsigned char v=(g_cnt1[g*36+t]>0.f)?1:0;
        vld[t]=v;
        if(v){ atomicAdd(&cnt[c],1.f); atomicAdd(&psx[c],qx); atomicAdd(&psy[c],qy); }
    }
    __syncthreads();
    if(t<25){
        float ic=1.f/fmaxf(cnt[t],1.f);
        ppx2[t]=psx[t]*ic; ppy2[t]=psy[t]*ic;
    }
    __syncthreads();
    for(int i=t;i<36*64;i+=256){
        int s=i>>6, f=i&63;
        if(vld[s]) atomicMax(&px[cl2[s]*64+f], encf(g_x2o[(g*36+s)*64+f]));
    }
    int ec=g_ecnt1[g];
    for(int i=t;i<ec;i+=256){
        unsigned r=g_el1[g*EPG+i];
        int a=cl2[r&255], b=cl2[(r>>8)&255];
        if(a!=b){
            int key=a*25+b;
            unsigned bit=1u<<(key&31);
            if(!(atomicOr(&bm[key>>5],bit)&bit)){
                int idx=atomicAdd(&ecnt,1);
                g_el2[g*EPG+idx]=(unsigned)a|((unsigned)b<<8);
                atomicAdd(&deg3s[b],1.f);
                float c0=fabsf(ppx2[a]-ppx2[b]), c1=fabsf(ppy2[a]-ppy2[b]);
                atomicMax(&cmax,__float_as_uint(fmaxf(c0,c1)));
            }
        }
    }
    __syncthreads();
    for(int i=t;i<25*64;i+=256){
        int s=i>>6, f=i&63;
        float c=cnt[s];
        float v=(c>0.f)? decf(px[i]) : 0.f;
        g_x3[(g*25+s)*64+f]=v;
        g_x3h[(g*25+s)*64+f]=__float2bfloat16(v);
        if(f==0){
            g_cnt2[g*25+s]=c;
            g_ppos2[(g*25+s)*2]=ppx2[s];
            g_ppos2[(g*25+s)*2+1]=ppy2[s];
            g_deg3[g*25+s]=deg3s[s];
        }
    }
    if(t==0){ g_ecnt2[g]=ecnt; redMaxU(&g_amax[2],cmax); }
}

// ---------------- stage-3 gather: 384 thr, dynamic smem (round-11 proven) ----------------
#define G3_PKW    0
#define G3_ACCS   (600*8)
#define G3_XS     (G3_ACCS+12*1600*4)
#define G3_PPX    (G3_XS+1600*4)
#define G3_PPY    (G3_PPX+25*4)
#define G3_INVD   (G3_PPY+25*4)
#define G3_OFFS   (G3_INVD+25*4)
#define G3_CUR    (G3_OFFS+26*4)
#define G3_PKA    (G3_CUR+25*4)
#define G3_BYTES  (G3_PKA+600*2+8)
__global__ __launch_bounds__(384) void k_gather3(){
    extern __shared__ char dyn3[];
    uint2* pkw=(uint2*)(dyn3+G3_PKW);
    float* accS=(float*)(dyn3+G3_ACCS);
    float* xs=(float*)(dyn3+G3_XS);
    float* ppx=(float*)(dyn3+G3_PPX);
    float* ppy=(float*)(dyn3+G3_PPY);
    float* invd=(float*)(dyn3+G3_INVD);
    int* offs=(int*)(dyn3+G3_OFFS);
    int* cursor=(int*)(dyn3+G3_CUR);
    unsigned short* pka=(unsigned short*)(dyn3+G3_PKA);
    int g=blockIdx.x, t=threadIdx.x, lane=t&31, w=t>>5;
    for(int i=t;i<25*64;i+=384) xs[i]=g_x3[g*25*64+i];
    if(t<25){
        float d=g_deg3[g*25+t];
        ppx[t]=g_ppos2[(g*25+t)*2]; ppy[t]=g_ppos2[(g*25+t)*2+1];
        invd[t]=1.f/fmaxf(d,1.f);
        cursor[t]=(int)d;
    }
    __syncthreads();
    if(t==0){
        int a=0;
#pragma unroll
        for(int i=0;i<25;i++){ int c=cursor[i]; offs[i]=a; a+=c; }
        offs[25]=a;
    }
    __syncthreads();
    int ec=offs[25];
    if(t<25) cursor[t]=offs[t];
    __syncthreads();
    float amax=fmaxf(__uint_as_float(g_amax[2]),1e-12f);
    float inv=0.5f/amax;
    for(int i=t;i<ec;i+=384){
        unsigned r=g_el2[g*EPG+i];
        int a=r&255, b=(r>>8)&255;
        float p0=(ppx[a]-ppx[b])*inv+0.5f;
        float p1=(ppy[a]-ppy[b])*inv+0.5f;
        float v0=fminf(fmaxf(p0,0.f),1.f)*4.f;
        float v1=fminf(fmaxf(p1,0.f),1.f)*4.f;
        float b0=fminf(floorf(v0),3.f), b1f=fminf(floorf(v1),3.f);
        float f0=v0-b0, f1=v1-b1f;
        int kb=(int)b0+5*(int)b1f;
        int j=atomicAdd(&cursor[b],1);
        pkw[j]=make_uint2(packbf2w((1.f-f0)*(1.f-f1), f0*(1.f-f1)),
                          packbf2w((1.f-f0)*f1,       f0*f1));
        pka[j]=(unsigned short)((a<<5)|kb);
    }
    __syncthreads();
    float* ac=&accS[w*1600];
    for(int b=w;b<25;b+=12){
#pragma unroll
        for(int k=0;k<25;k++){ ac[k*64+lane]=0.f; ac[k*64+32+lane]=0.f; }
        int s0=offs[b], s1=offs[b+1];
        for(int j=s0;j<s1;j++){
            uint2 p=pkw[j];
            unsigned q=pka[j];
            int a=q>>5, kb=q&31;
            float x0=xs[a*64+lane], x1=xs[a*64+32+lane];
            float wA=upperf(p.x), wB=lowerf(p.x), wC=upperf(p.y), wD=lowerf(p.y);
            float* pb=&ac[kb*64+lane];
            pb[0]      +=wA*x0; pb[32]     +=wA*x1;
            pb[64]     +=wB*x0; pb[96]     +=wB*x1;
            pb[5*64]   +=wC*x0; pb[5*64+32]+=wC*x1;
            pb[6*64]   +=wD*x0; pb[6*64+32]+=wD*x1;
        }
        float iv=invd[b];
#pragma unroll
        for(int k=0;k<25;k++){
            float v0=ac[k*64+lane]*iv, v1=ac[k*64+32+lane]*iv;
            float n0=__shfl_down_sync(0xffffffffu,v0,1);
            float n1=__shfl_down_sync(0xffffffffu,v1,1);
            if(!(lane&1)){
                unsigned* po=(unsigned*)&g_acc3h[(size_t)(g*625+b*25+k)*64];
                po[lane>>1]=packbf(v0,n0);
                po[16+(lane>>1)]=packbf(v1,n1);
            }
        }
    }
}

// ---------------- fused final pool + FC head (per graph) ----------------
__global__ __launch_bounds__(128) void k_headg(const float* __restrict__ fw1,
        const float* __restrict__ fb1, const float* __restrict__ fw2,
        const float* __restrict__ fb2, float* __restrict__ out){
    __shared__ unsigned enc4[4*64];
    __shared__ unsigned any[4];
    __shared__ float in[256];
    __shared__ float h[128];
    __shared__ float lg[10];
    __shared__ float lse;
    int g=blockIdx.x, t=threadIdx.x;
    for(int i=t;i<256;i+=128) enc4[i]=encf(-1e30f);
    if(t<4) any[t]=0u;
    __syncthreads();
    for(int i=t;i<25*64;i+=128){
        int n=i>>6, f=i&63;
        if(g_cnt2[g*25+n]>0.f){
            float qx=g_ppos2[(g*25+n)*2], qy=g_ppos2[(g*25+n)*2+1];
            int c0=min(max((int)floorf(qx/14.f),0),1);
            int c1=min(max((int)floorf(qy/14.f),0),1);
            int cell=c1*2+c0;
            atomicMax(&enc4[cell*64+f], encf(g_x3o[(g*25+n)*64+f]));
            if(f==0) atomicOr(&any[cell],1u);
        }
    }
    __syncthreads();
    for(int i=t;i<256;i+=128)
        in[i]=any[i>>6]? decf(enc4[i]) : 0.f;
    __syncthreads();
    float s=fb1[t];
    const float4* wr=(const float4*)(fw1+(size_t)t*256);
#pragma unroll 8
    for(int i=0;i<64;i++){
        float4 w=wr[i];
        const float4 v=*(const float4*)&in[i*4];
        s+=w.x*v.x+w.y*v.y+w.z*v.z+w.w*v.w;
    }
    h[t]=eluf(s);
    __syncthreads();
    if(t<10){
        float l=fb2[t];
        for(int i=0;i<128;i++) l+=h[i]*fw2[t*128+i];
        lg[t]=l;
    }
    __syncthreads();
    if(t==0){
        float m=lg[0];
        for(int i=1;i<10;i++) m=fmaxf(m,lg[i]);
        float ss=0.f;
        for(int i=0;i<10;i++) ss+=expf(lg[i]-m);
        lse=m+logf(ss);
    }
    __syncthreads();
    if(t<10) out[g*10+t]=lg[t]-lse;
}

// ---------------- launch ----------------
extern "C" void kernel_launch(void* const* d_in, const int* in_sizes, int n_in,
                              void* d_out, int out_size){
    const float* x   =(const float*)d_in[0];
    const float* pos =(const float*)d_in[1];
    const int*   src =(const int*)  d_in[2];
    const int*   dst =(const int*)  d_in[3];
    const float* W1  =(const float*)d_in[4];
    const float* r1  =(const float*)d_in[5];
    const float* b1  =(const float*)d_in[6];
    const float* W2  =(const float*)d_in[7];
    const float* r2  =(const float*)d_in[8];
    const float* b2  =(const float*)d_in[9];
    const float* W3  =(const float*)d_in[10];
    const float* r3  =(const float*)d_in[11];
    const float* b3  =(const float*)d_in[12];
    const float* fw1 =(const float*)d_in[13];
    const float* fb1 =(const float*)d_in[14];
    const float* fw2 =(const float*)d_in[15];
    const float* fb2 =(const float*)d_in[16];
    float* out=(float*)d_out;

    __nv_bfloat16 *pA2h,*pX2h,*pA3h,*pX3h;
    unsigned *pWp2,*pWp3;
    float *pX2o,*pX3o;
    cudaGetSymbolAddress((void**)&pA2h, g_acc2h);
    cudaGetSymbolAddress((void**)&pX2h, g_x2h);
    cudaGetSymbolAddress((void**)&pA3h, g_acc3h);
    cudaGetSymbolAddress((void**)&pX3h, g_x3h);
    cudaGetSymbolAddress((void**)&pWp2, g_Wp2);
    cudaGetSymbolAddress((void**)&pWp3, g_Wp3);
    cudaGetSymbolAddress((void**)&pX2o, g_x2o);
    cudaGetSymbolAddress((void**)&pX3o, g_x3o);

    static int attrdone=0;
    if(!attrdone){
        cudaFuncSetAttribute(k_gather2, cudaFuncAttributeMaxDynamicSharedMemorySize, G2_BYTES);
        cudaFuncSetAttribute(k_gather3, cudaFuncAttributeMaxDynamicSharedMemorySize, G3_BYTES);
        attrdone=1;
    }

    k_reset0<<<1,32>>>();
    k_prep<<<BB+(416*64+832*64+255)/256,256>>>(pos,src,dst,W2,r2,W3,r3);
    k_stage1<<<BB,512>>>(x,pos,src,dst,W1,r1,b1);
    k_gather2<<<BB,512,G2_BYTES>>>();
    k_convB<800,32><<<S1C/128,256>>>(pA2h,pX2h,pWp2,b2,pX2o);
    k_pool2g<<<BB,256>>>();
    k_gather3<<<BB,384,G3_BYTES>>>();
    k_convB<1600,64><<<S2C/128,256>>>(pA3h,pX3h,pWp3,b3,pX3o);
    k_headg<<<BB,128>>>(fw1,fb1,fw2,fb2,out);
}

// round 15
// speedup vs baseline: 1.0932x; 1.0291x over previous
#include <cuda_runtime.h>
#include <cuda_bf16.h>

#define NN   76800
#define EE   1425408
#define BB   1024
#define EPG  1392
#define S1C  36864
#define S2C  25600

// ---------------- device scratch ----------------
__device__ __nv_bfloat16 g_x2h[S1C*32];
__device__ float g_cnt1[S1C];
__device__ float g_ppos1[S1C*2];
__device__ unsigned g_el1[EE];
__device__ int   g_ecnt1[BB];
__device__ float g_deg2[S1C];
__device__ __nv_bfloat16 g_acc2h[S1C*25*32];
__device__ float g_x2o[S1C*64];
__device__ __nv_bfloat16 g_x3h[S2C*64];
__device__ float g_cnt2[S2C];
__device__ float g_ppos2[S2C*2];
__device__ unsigned g_el2[EE];
__device__ int   g_ecnt2[BB];
__device__ float g_deg3[S2C];
__device__ __nv_bfloat16 g_acc3h[S2C*25*64];
__device__ float g_x3o[S2C*64];
__device__ unsigned g_amax[4];
__device__ unsigned g_Wp2[416*64];
__device__ unsigned g_Wp3[832*64];

// ---------------- helpers ----------------
__device__ __forceinline__ unsigned encf(float f){
    unsigned u=__float_as_uint(f);
    return (u&0x80000000u)? ~u : (u|0x80000000u);
}
__device__ __forceinline__ float decf(unsigned u){
    return (u&0x80000000u)? __uint_as_float(u&0x7FFFFFFFu) : __uint_as_float(~u);
}
__device__ __forceinline__ float eluf(float x){ return x>0.f ? x : expm1f(x); }
__device__ __forceinline__ void redMaxU(unsigned* p, unsigned v){
    asm volatile("red.global.max.u32 [%0], %1;" :: "l"(p), "r"(v) : "memory");
}
__device__ __forceinline__ unsigned packbf(float a, float b){
    __nv_bfloat162 h=__floats2bfloat162_rn(a,b);
    return *reinterpret_cast<unsigned*>(&h);
}
__device__ __forceinline__ unsigned packbf2w(float hi, float lo){
    unsigned h=(unsigned)__bfloat16_as_ushort(__float2bfloat16(hi));
    unsigned l=(unsigned)__bfloat16_as_ushort(__float2bfloat16(lo));
    return (h<<16)|l;
}
__device__ __forceinline__ float upperf(unsigned u){ return __uint_as_float(u&0xFFFF0000u); }
__device__ __forceinline__ float lowerf(unsigned u){ return __uint_as_float(u<<16); }
__device__ __forceinline__ void mma_bf16(float* d, unsigned a0,unsigned a1,unsigned a2,unsigned a3,
                                         unsigned b0, unsigned b1){
    asm("mma.sync.aligned.m16n8k16.row.col.f32.bf16.bf16.f32 "
        "{%0,%1,%2,%3}, {%4,%5,%6,%7}, {%8,%9}, {%0,%1,%2,%3};"
        : "+f"(d[0]),"+f"(d[1]),"+f"(d[2]),"+f"(d[3])
        : "r"(a0),"r"(a1),"r"(a2),"r"(a3),"r"(b0),"r"(b1));
}

// ---------------- fused prep: per-graph amax (blocks 0..1023) + weight pack ----------------
__global__ void k_prep(const float* __restrict__ pos, const int* __restrict__ src,
                       const int* __restrict__ dst,
                       const float* __restrict__ W2, const float* __restrict__ r2,
                       const float* __restrict__ W3, const float* __restrict__ r3){
    int blk=blockIdx.x, t=threadIdx.x;
    if(blk<BB){
        __shared__ unsigned wm[8];
        int g=blk;
        unsigned cand=0u;
        for(int i=t;i<EPG;i+=256){
            int e=g*EPG+i;
            int s=src[e], d=dst[e];
            float c0=fabsf(pos[2*s]-pos[2*d]);
            float c1=fabsf(pos[2*s+1]-pos[2*d+1]);
            cand=max(cand,__float_as_uint(fmaxf(c0,c1)));
        }
        unsigned m=__reduce_max_sync(0xffffffffu,cand);
        if((t&31)==0) wm[t>>5]=m;
        __syncthreads();
        if(t==0){
            unsigned mm=0;
#pragma unroll
            for(int i=0;i<8;i++) mm=max(mm,wm[i]);
            redMaxU(&g_amax[0],mm);
        }
        return;
    }
    int i=(blk-BB)*256+t;
    if(i<416*64){
        int kp=i>>6, n=i&63;
        float lo,hi;
        if(kp<400){ lo=W2[(2*kp)*64+n]; hi=W2[(2*kp+1)*64+n]; }
        else      { int q=kp-400; lo=r2[(2*q)*64+n]; hi=r2[(2*q+1)*64+n]; }
        g_Wp2[i]=packbf(lo,hi);
    }
    int j=i-416*64;
    if(j>=0 && j<832*64){
        int kp=j>>6, n=j&63;
        float lo,hi;
        if(kp<800){ lo=W3[(2*kp)*64+n]; hi=W3[(2*kp+1)*64+n]; }
        else      { int q=kp-800; lo=r3[(2*q)*64+n]; hi=r3[(2*q+1)*64+n]; }
        g_Wp3[j]=packbf(lo,hi);
    }
}
__global__ void k_reset0(){ if(threadIdx.x<4) g_amax[threadIdx.x]=0u; }

// ---------------- fused stage 1 (256 threads): scatter + conv1 + pool1 + dedup1 ----------------
__global__ __launch_bounds__(256) void k_stage1(const float* __restrict__ x,
        const float* __restrict__ pos, const int* __restrict__ src,
        const int* __restrict__ dst, const float* __restrict__ W1,
        const float* __restrict__ r1, const float* __restrict__ b1){
    int g=blockIdx.x, t=threadIdx.x;
    __shared__ float acc[75*25];
    __shared__ float deg[75];
    __shared__ float posx[75], posy[75], xin[75];
    __shared__ float W1s[800], r1s[32], b1s[32];
    __shared__ unsigned px[36*32];
    __shared__ float cnt[36], psx[36], psy[36], ppx[36], ppy[36], deg2s[36];
    __shared__ unsigned char cl[75];
    __shared__ unsigned bm[41];
    __shared__ int ecnt;
    __shared__ unsigned cmax;

    for(int i=t;i<1875;i+=256) acc[i]=0.f;
    for(int i=t;i<800;i+=256) W1s[i]=W1[i];
    if(t<75){
        deg[t]=0.f;
        float2 p=*(const float2*)&pos[(g*75+t)*2];
        posx[t]=p.x; posy[t]=p.y;
        xin[t]=x[g*75+t];
    }
    if(t>=96 && t<128){ r1s[t-96]=r1[t-96]; b1s[t-96]=b1[t-96]; }
    if(t>=128 && t<164){ int c=t-128; cnt[c]=0.f; psx[c]=0.f; psy[c]=0.f; deg2s[c]=0.f; }
    if(t>=164 && t<205) bm[t-164]=0u;
    if(t==0){ ecnt=0; cmax=0u; }
    for(int i=t;i<1152;i+=256) px[i]=encf(-1e30f);
    __syncthreads();
    if(t<75){
        int c0=min(max((int)floorf(posx[t]/5.f),0),5);
        int c1=min(max((int)floorf(posy[t]/5.f),0),5);
        int c=c1*6+c0;
        cl[t]=(unsigned char)c;
        atomicAdd(&cnt[c],1.f);
        atomicAdd(&psx[c],posx[t]);
        atomicAdd(&psy[c],posy[t]);
    }
    __syncthreads();
    if(t<36){
        float ic=1.f/fmaxf(cnt[t],1.f);
        ppx[t]=psx[t]*ic; ppy[t]=psy[t]*ic;
    }
    __syncthreads();
    float amax=fmaxf(__uint_as_float(g_amax[0]),1e-12f);
    float inv=0.5f/amax;
    for(int i=t;i<EPG;i+=256){
        int e=g*EPG+i;
        int s=src[e]-g*75, d=dst[e]-g*75;
        float p0=(posx[s]-posx[d])*inv+0.5f;
        float p1=(posy[s]-posy[d])*inv+0.5f;
        float v0=fminf(fmaxf(p0,0.f),1.f)*4.f;
        float v1=fminf(fmaxf(p1,0.f),1.f)*4.f;
        float b0=fminf(floorf(v0),3.f), b1f=fminf(floorf(v1),3.f);
        int i0=(int)b0, i1=(int)b1f;
        float f0=v0-b0, f1=v1-b1f;
        float xs=xin[s];
        float* base=&acc[d*25+i0+5*i1];
        atomicAdd(base,   (1.f-f0)*(1.f-f1)*xs);
        atomicAdd(base+1, f0*(1.f-f1)*xs);
        atomicAdd(base+5, (1.f-f0)*f1*xs);
        atomicAdd(base+6, f0*f1*xs);
        atomicAdd(&deg[d],1.f);
        int a=cl[s], b=cl[d];
        if(a!=b){
            int key=a*36+b;
            unsigned bit=1u<<(key&31);
            if(!(atomicOr(&bm[key>>5],bit)&bit)){
                int idx=atomicAdd(&ecnt,1);
                g_el1[g*EPG+idx]=(unsigned)a|((unsigned)b<<8);
                atomicAdd(&deg2s[b],1.f);
                float c0=fabsf(ppx[a]-ppx[b]), c1=fabsf(ppy[a]-ppy[b]);
                atomicMax(&cmax,__float_as_uint(fmaxf(c0,c1)));
            }
        }
    }
    __syncthreads();
    for(int i=t;i<2400;i+=256){
        int n=i>>5, o=i&31;
        const float* ar=&acc[n*25];
        float s=0.f;
#pragma unroll
        for(int k=0;k<25;k++) s+=ar[k]*W1s[k*32+o];
        s=s/fmaxf(deg[n],1.f)+xin[n]*r1s[o]+b1s[o];
        atomicMax(&px[cl[n]*32+o], encf(eluf(s)));
    }
    __syncthreads();
    for(int i=t;i<1152;i+=256){
        int s=i>>5, f=i&31;
        float c=cnt[s];
        float v=(c>0.f)? decf(px[i]) : 0.f;
        g_x2h[(g*36+s)*32+f]=__float2bfloat16(v);
        if(f==0){
            g_cnt1[g*36+s]=c;
            g_ppos1[(g*36+s)*2]=ppx[s];
            g_ppos1[(g*36+s)*2+1]=ppy[s];
            g_deg2[g*36+s]=deg2s[s];
        }
    }
    if(t==0){ g_ecnt1[g]=ecnt; redMaxU(&g_amax[1],cmax); }
}

// ---------------- stage-2 gather: 512 thr, dynamic smem ----------------
#define G2_PKW    0
#define G2_ACCS   (1260*8)
#define G2_XS     (G2_ACCS+16*800*4)
#define G2_PPX    (G2_XS+1152*4)
#define G2_PPY    (G2_PPX+36*4)
#define G2_INVD   (G2_PPY+36*4)
#define G2_OFFS   (G2_INVD+36*4)
#define G2_CUR    (G2_OFFS+37*4)
#define G2_PKA    (G2_CUR+36*4)
#define G2_BYTES  (G2_PKA+1260*2+8)
__global__ __launch_bounds__(512) void k_gather2(){
    extern __shared__ char dyn2[];
    uint2* pkw=(uint2*)(dyn2+G2_PKW);
    float* accS=(float*)(dyn2+G2_ACCS);
    float* xs=(float*)(dyn2+G2_XS);
    float* ppx=(float*)(dyn2+G2_PPX);
    float* ppy=(float*)(dyn2+G2_PPY);
    float* invd=(float*)(dyn2+G2_INVD);
    int* offs=(int*)(dyn2+G2_OFFS);
    int* cursor=(int*)(dyn2+G2_CUR);
    unsigned short* pka=(unsigned short*)(dyn2+G2_PKA);
    int g=blockIdx.x, t=threadIdx.x, lane=t&31, w=t>>5;
    for(int i=t;i<36*32;i+=512) xs[i]=__bfloat162float(g_x2h[g*36*32+i]);
    if(t<36){
        float d=g_deg2[g*36+t];
        ppx[t]=g_ppos1[(g*36+t)*2]; ppy[t]=g_ppos1[(g*36+t)*2+1];
        invd[t]=1.f/fmaxf(d,1.f);
        cursor[t]=(int)d;
    }
    __syncthreads();
    if(t==0){
        int a=0;
#pragma unroll
        for(int i=0;i<36;i++){ int c=cursor[i]; offs[i]=a; a+=c; }
        offs[36]=a;
    }
    __syncthreads();
    int ec=offs[36];
    if(t<36) cursor[t]=offs[t];
    __syncthreads();
    float amax=fmaxf(__uint_as_float(g_amax[1]),1e-12f);
    float inv=0.5f/amax;
    for(int i=t;i<ec;i+=512){
        unsigned r=g_el1[g*EPG+i];
        int a=r&255, b=(r>>8)&255;
        float p0=(ppx[a]-ppx[b])*inv+0.5f;
        float p1=(ppy[a]-ppy[b])*inv+0.5f;
        float v0=fminf(fmaxf(p0,0.f),1.f)*4.f;
        float v1=fminf(fmaxf(p1,0.f),1.f)*4.f;
        float b0=fminf(floorf(v0),3.f), b1f=fminf(floorf(v1),3.f);
        float f0=v0-b0, f1=v1-b1f;
        int kb=(int)b0+5*(int)b1f;
        int j=atomicAdd(&cursor[b],1);
        pkw[j]=make_uint2(packbf2w((1.f-f0)*(1.f-f1), f0*(1.f-f1)),
                          packbf2w((1.f-f0)*f1,       f0*f1));
        pka[j]=(unsigned short)((a<<5)|kb);
    }
    __syncthreads();
    float* ac=&accS[w*800];
    for(int b=w;b<36;b+=16){
#pragma unroll
        for(int k=0;k<25;k++) ac[k*32+lane]=0.f;
        int s0=offs[b], s1=offs[b+1];
        for(int j=s0;j<s1;j++){
            uint2 p=pkw[j];
            unsigned q=pka[j];
            int a=q>>5, kb=q&31;
            float xv=xs[a*32+lane];
            float* pb=&ac[kb*32+lane];
            pb[0]    +=upperf(p.x)*xv;
            pb[32]   +=lowerf(p.x)*xv;
            pb[5*32] +=upperf(p.y)*xv;
            pb[6*32] +=lowerf(p.y)*xv;
        }
        float iv=invd[b];
#pragma unroll
        for(int k=0;k<25;k++){
            float v=ac[k*32+lane]*iv;
            float nx=__shfl_down_sync(0xffffffffu,v,1);
            if(!(lane&1)){
                unsigned* po=(unsigned*)&g_acc2h[(size_t)(g*900+b*25+k)*32];
                po[lane>>1]=packbf(v,nx);
            }
        }
    }
}

// ---------------- bf16 tensor-core conv GEMM (single-buffered 128-row tile) ----------------
template<int KK,int FIN>
__global__ __launch_bounds__(256) void k_convB(
    const __nv_bfloat16* __restrict__ A, const __nv_bfloat16* __restrict__ Xh,
    const unsigned* __restrict__ Wp, const float* __restrict__ Bv,
    float* __restrict__ Out)
{
    constexpr int nTA=KK/32, nT=(KK+FIN)/32;
    __shared__ unsigned As2[16][136];
    __shared__ __align__(16) unsigned Ws2[16][72];
    int t=threadIdx.x, lane=t&31, w=t>>5;
    int gid=lane>>2, tig=lane&3;
    int n0=blockIdx.x*128;
    int m0=w*16;
    int r0=n0+m0+gid;
    float C[8][4];
#pragma unroll
    for(int j=0;j<8;j++){ C[j][0]=0.f; C[j][1]=0.f; C[j][2]=0.f; C[j][3]=0.f; }
    int ar=t>>1, half=t&1;
    int wkp=t>>4, wnb=(t&15)*4;
    uint4 pa0,pa1,pw;
    auto loadT=[&](int j){
        const __nv_bfloat16* Ap=(j<nTA)? A+(size_t)(n0+ar)*KK+j*32+half*16
                                       : Xh+(size_t)(n0+ar)*FIN+(j-nTA)*32+half*16;
        pa0=*(const uint4*)Ap;
        pa1=*(const uint4*)(Ap+8);
        pw =*(const uint4*)&Wp[(size_t)(j*16+wkp)*64+wnb];
    };
    loadT(0);
    for(int j=0;j<nT;j++){
        __syncthreads();
        int kb=half*8;
        As2[kb+0][ar]=pa0.x; As2[kb+1][ar]=pa0.y; As2[kb+2][ar]=pa0.z; As2[kb+3][ar]=pa0.w;
        As2[kb+4][ar]=pa1.x; As2[kb+5][ar]=pa1.y; As2[kb+6][ar]=pa1.z; As2[kb+7][ar]=pa1.w;
        *(uint4*)&Ws2[wkp][wnb]=pw;
        __syncthreads();
        if(j+1<nT) loadT(j+1);
#pragma unroll
        for(int s8=0;s8<16;s8+=8){
            unsigned a0=As2[s8+tig  ][m0+gid];
            unsigned a1=As2[s8+tig  ][m0+8+gid];
            unsigned a2=As2[s8+tig+4][m0+gid];
            unsigned a3=As2[s8+tig+4][m0+8+gid];
#pragma unroll
            for(int jj=0;jj<8;jj++){
                unsigned b0=Ws2[s8+tig  ][jj*8+gid];
                unsigned b1=Ws2[s8+tig+4][jj*8+gid];
                mma_bf16(C[jj],a0,a1,a2,a3,b0,b1);
            }
        }
    }
#pragma unroll
    for(int jj=0;jj<8;jj++){
        int c=jj*8+2*tig;
        float bv0=Bv[c], bv1=Bv[c+1];
        float2 o;
        o.x=eluf(C[jj][0]+bv0); o.y=eluf(C[jj][1]+bv1);
        *(float2*)&Out[(size_t)r0*64+c]=o;
        o.x=eluf(C[jj][2]+bv0); o.y=eluf(C[jj][3]+bv1);
        *(float2*)&Out[(size_t)(r0+8)*64+c]=o;
    }
}

// ---------------- pool2 + dedup2 fused (per graph) ----------------
__global__ __launch_bounds__(256) void k_pool2g(){
    int g=blockIdx.x, t=threadIdx.x;
    __shared__ unsigned px[25*64];
    __shared__ float cnt[25], psx[25], psy[25], ppx2[25], ppy2[25], deg3s[25];
    __shared__ unsigned char cl2[36], vld[36];
    __shared__ unsigned bm[20];
    __shared__ int ecnt;
    __shared__ unsigned cmax;
    for(int i=t;i<25*64;i+=256) px[i]=encf(-1e30f);
    if(t<25){ cnt[t]=0.f; psx[t]=0.f; psy[t]=0.f; deg3s[t]=0.f; }
    if(t>=32 && t<52) bm[t-32]=0u;
    if(t==0){ ecnt=0; cmax=0u; }
    __syncthreads();
    if(t<36){
        float qx=g_ppos1[(g*36+t)*2], qy=g_ppos1[(g*36+t)*2+1];
        int c0=min(max((int)floorf(qx/7.f),0),4);
        int c1=min(max((int)floorf(qy/7.f),0),4);
        int c=c1*5+c0;
        cl2[t]=(unsigned char)c;
        unsigned char v=(g_cnt1[g*36+t]>0.f)?1:0;
        vld[t]=v;
        if(v){ atomicAdd(&cnt[c],1.f); atomicAdd(&psx[c],qx); atomicAdd(&psy[c],qy); }
    }
    __syncthreads();
    if(t<25){
        float ic=1.f/fmaxf(cnt[t],1.f);
        ppx2[t]=psx[t]*ic; ppy2[t]=psy[t]*ic;
    }
    __syncthreads();
    for(int i=t;i<36*64;i+=256){
        int s=i>>6, f=i&63;
        if(vld[s]) atomicMax(&px[cl2[s]*64+f], encf(g_x2o[(g*36+s)*64+f]));
    }
    int ec=g_ecnt1[g];
    for(int i=t;i<ec;i+=256){
        unsigned r=g_el1[g*EPG+i];
        int a=cl2[r&255], b=cl2[(r>>8)&255];
        if(a!=b){
            int key=a*25+b;
            unsigned bit=1u<<(key&31);
            if(!(atomicOr(&bm[key>>5],bit)&bit)){
                int idx=atomicAdd(&ecnt,1);
                g_el2[g*EPG+idx]=(unsigned)a|((unsigned)b<<8);
                atomicAdd(&deg3s[b],1.f);
                float c0=fabsf(ppx2[a]-ppx2[b]), c1=fabsf(ppy2[a]-ppy2[b]);
                atomicMax(&cmax,__float_as_uint(fmaxf(c0,c1)));
            }
        }
    }
    __syncthreads();
    for(int i=t;i<25*64;i+=256){
        int s=i>>6, f=i&63;
        float c=cnt[s];
        float v=(c>0.f)? decf(px[i]) : 0.f;
        g_x3h[(g*25+s)*64+f]=__float2bfloat16(v);
        if(f==0){
            g_cnt2[g*25+s]=c;
            g_ppos2[(g*25+s)*2]=ppx2[s];
            g_ppos2[(g*25+s)*2+1]=ppy2[s];
            g_deg3[g*25+s]=deg3s[s];
        }
    }
    if(t==0){ g_ecnt2[g]=ecnt; redMaxU(&g_amax[2],cmax); }
}

// ---------------- stage-3 gather: 384 thr, dynamic smem ----------------
#define G3_PKW    0
#define G3_ACCS   (600*8)
#define G3_XS     (G3_ACCS+12*1600*4)
#define G3_PPX    (G3_XS+1600*4)
#define G3_PPY    (G3_PPX+25*4)
#define G3_INVD   (G3_PPY+25*4)
#define G3_OFFS   (G3_INVD+25*4)
#define G3_CUR    (G3_OFFS+26*4)
#define G3_PKA    (G3_CUR+25*4)
#define G3_BYTES  (G3_PKA+600*2+8)
__global__ __launch_bounds__(384) void k_gather3(){
    extern __shared__ char dyn3[];
    uint2* pkw=(uint2*)(dyn3+G3_PKW);
    float* accS=(float*)(dyn3+G3_ACCS);
    float* xs=(float*)(dyn3+G3_XS);
    float* ppx=(float*)(dyn3+G3_PPX);
    float* ppy=(float*)(dyn3+G3_PPY);
    float* invd=(float*)(dyn3+G3_INVD);
    int* offs=(int*)(dyn3+G3_OFFS);
    int* cursor=(int*)(dyn3+G3_CUR);
    unsigned short* pka=(unsigned short*)(dyn3+G3_PKA);
    int g=blockIdx.x, t=threadIdx.x, lane=t&31, w=t>>5;
    for(int i=t;i<25*64;i+=384) xs[i]=__bfloat162float(g_x3h[g*25*64+i]);
    if(t<25){
        float d=g_deg3[g*25+t];
        ppx[t]=g_ppos2[(g*25+t)*2]; ppy[t]=g_ppos2[(g*25+t)*2+1];
        invd[t]=1.f/fmaxf(d,1.f);
        cursor[t]=(int)d;
    }
    __syncthreads();
    if(t==0){
        int a=0;
#pragma unroll
        for(int i=0;i<25;i++){ int c=cursor[i]; offs[i]=a; a+=c; }
        offs[25]=a;
    }
    __syncthreads();
    int ec=offs[25];
    if(t<25) cursor[t]=offs[t];
    __syncthreads();
    float amax=fmaxf(__uint_as_float(g_amax[2]),1e-12f);
    float inv=0.5f/amax;
    for(int i=t;i<ec;i+=384){
        unsigned r=g_el2[g*EPG+i];
        int a=r&255, b=(r>>8)&255;
        float p0=(ppx[a]-ppx[b])*inv+0.5f;
        float p1=(ppy[a]-ppy[b])*inv+0.5f;
        float v0=fminf(fmaxf(p0,0.f),1.f)*4.f;
        float v1=fminf(fmaxf(p1,0.f),1.f)*4.f;
        float b0=fminf(floorf(v0),3.f), b1f=fminf(floorf(v1),3.f);
        float f0=v0-b0, f1=v1-b1f;
        int kb=(int)b0+5*(int)b1f;
        int j=atomicAdd(&cursor[b],1);
        pkw[j]=make_uint2(packbf2w((1.f-f0)*(1.f-f1), f0*(1.f-f1)),
                          packbf2w((1.f-f0)*f1,       f0*f1));
        pka[j]=(unsigned short)((a<<5)|kb);
    }
    __syncthreads();
    float* ac=&accS[w*1600];
    for(int b=w;b<25;b+=12){
#pragma unroll
        for(int k=0;k<25;k++){ ac[k*64+lane]=0.f; ac[k*64+32+lane]=0.f; }
        int s0=offs[b], s1=offs[b+1];
        for(int j=s0;j<s1;j++){
            uint2 p=pkw[j];
            unsigned q=pka[j];
            int a=q>>5, kb=q&31;
            float x0=xs[a*64+lane], x1=xs[a*64+32+lane];
            float wA=upperf(p.x), wB=lowerf(p.x), wC=upperf(p.y), wD=lowerf(p.y);
            float* pb=&ac[kb*64+lane];
            pb[0]      +=wA*x0; pb[32]     +=wA*x1;
            pb[64]     +=wB*x0; pb[96]     +=wB*x1;
            pb[5*64]   +=wC*x0; pb[5*64+32]+=wC*x1;
            pb[6*64]   +=wD*x0; pb[6*64+32]+=wD*x1;
        }
        float iv=invd[b];
#pragma unroll
        for(int k=0;k<25;k++){
            float v0=ac[k*64+lane]*iv, v1=ac[k*64+32+lane]*iv;
            float n0=__shfl_down_sync(0xffffffffu,v0,1);
            float n1=__shfl_down_sync(0xffffffffu,v1,1);
            if(!(lane&1)){
                unsigned* po=(unsigned*)&g_acc3h[(size_t)(g*625+b*25+k)*64];
                po[lane>>1]=packbf(v0,n0);
                po[16+(lane>>1)]=packbf(v1,n1);
            }
        }
    }
}

// ---------------- fused final pool + FC head (per graph) ----------------
__global__ __launch_bounds__(128) void k_headg(const float* __restrict__ fw1,
        const float* __restrict__ fb1, const float* __restrict__ fw2,
        const float* __restrict__ fb2, float* __restrict__ out){
    __shared__ unsigned enc4[4*64];
    __shared__ unsigned any[4];
    __shared__ float in[256];
    __shared__ float h[128];
    __shared__ float lg[10];
    __shared__ float lse;
    int g=blockIdx.x, t=threadIdx.x;
    for(int i=t;i<256;i+=128) enc4[i]=encf(-1e30f);
    if(t<4) any[t]=0u;
    __syncthreads();
    for(int i=t;i<25*64;i+=128){
        int n=i>>6, f=i&63;
        if(g_cnt2[g*25+n]>0.f){
            float qx=g_ppos2[(g*25+n)*2], qy=g_ppos2[(g*25+n)*2+1];
            int c0=min(max((int)floorf(qx/14.f),0),1);
            int c1=min(max((int)floorf(qy/14.f),0),1);
            int cell=c1*2+c0;
            atomicMax(&enc4[cell*64+f], encf(g_x3o[(g*25+n)*64+f]));
            if(f==0) atomicOr(&any[cell],1u);
        }
    }
    __syncthreads();
    for(int i=t;i<256;i+=128)
        in[i]=any[i>>6]? decf(enc4[i]) : 0.f;
    __syncthreads();
    float s=fb1[t];
    const float4* wr=(const float4*)(fw1+(size_t)t*256);
#pragma unroll 8
    for(int i=0;i<64;i++){
        float4 w=wr[i];
        const float4 v=*(const float4*)&in[i*4];
        s+=w.x*v.x+w.y*v.y+w.z*v.z+w.w*v.w;
    }
    h[t]=eluf(s);
    __syncthreads();
    if(t<10){
        float l=fb2[t];
        for(int i=0;i<128;i++) l+=h[i]*fw2[t*128+i];
        lg[t]=l;
    }
    __syncthreads();
    if(t==0){
        float m=lg[0];
        for(int i=1;i<10;i++) m=fmaxf(m,lg[i]);
        float ss=0.f;
        for(int i=0;i<10;i++) ss+=expf(lg[i]-m);
        lse=m+logf(ss);
    }
    __syncthreads();
    if(t<10) out[g*10+t]=lg[t]-lse;
}

// ---------------- launch ----------------
extern "C" void kernel_launch(void* const* d_in, const int* in_sizes, int n_in,
                              void* d_out, int out_size){
    const float* x   =(const float*)d_in[0];
    const float* pos =(const float*)d_in[1];
    const int*   src =(const int*)  d_in[2];
    const int*   dst =(const int*)  d_in[3];
    const float* W1  =(const float*)d_in[4];
    const float* r1  =(const float*)d_in[5];
    const float* b1  =(const float*)d_in[6];
    const float* W2  =(const float*)d_in[7];
    const float* r2  =(const float*)d_in[8];
    const float* b2  =(const float*)d_in[9];
    const float* W3  =(const float*)d_in[10];
    const float* r3  =(const float*)d_in[11];
    const float* b3  =(const float*)d_in[12];
    const float* fw1 =(const float*)d_in[13];
    const float* fb1 =(const float*)d_in[14];
    const float* fw2 =(const float*)d_in[15];
    const float* fb2 =(const float*)d_in[16];
    float* out=(float*)d_out;

    __nv_bfloat16 *pA2h,*pX2h,*pA3h,*pX3h;
    unsigned *pWp2,*pWp3;
    float *pX2o,*pX3o;
    cudaGetSymbolAddress((void**)&pA2h, g_acc2h);
    cudaGetSymbolAddress((void**)&pX2h, g_x2h);
    cudaGetSymbolAddress((void**)&pA3h, g_acc3h);
    cudaGetSymbolAddress((void**)&pX3h, g_x3h);
    cudaGetSymbolAddress((void**)&pWp2, g_Wp2);
    cudaGetSymbolAddress((void**)&pWp3, g_Wp3);
    cudaGetSymbolAddress((void**)&pX2o, g_x2o);
    cudaGetSymbolAddress((void**)&pX3o, g_x3o);

    static int attrdone=0;
    if(!attrdone){
        cudaFuncSetAttribute(k_gather2, cudaFuncAttributeMaxDynamicSharedMemorySize, G2_BYTES);
        cudaFuncSetAttribute(k_gather3, cudaFuncAttributeMaxDynamicSharedMemorySize, G3_BYTES);
        attrdone=1;
    }

    k_reset0<<<1,32>>>();
    k_prep<<<BB+(416*64+832*64+255)/256,256>>>(pos,src,dst,W2,r2,W3,r3);
    k_stage1<<<BB,256>>>(x,pos,src,dst,W1,r1,b1);
    k_gather2<<<BB,512,G2_BYTES>>>();
    k_convB<800,32><<<S1C/128,256>>>(pA2h,pX2h,pWp2,b2,pX2o);
    k_pool2g<<<BB,256>>>();
    k_gather3<<<BB,384,G3_BYTES>>>();
    k_convB<1600,64><<<S2C/128,256>>>(pA3h,pX3h,pWp3,b3,pX3o);
    k_headg<<<BB,128>>>(fw1,fb1,fw2,fb2,out);
}